// round 2
// baseline (speedup 1.0000x reference)
#include <cuda_runtime.h>
#include <cuda_bf16.h>
#include <math.h>

// ---------------- static problem shape ----------------
#define BATCH     2
#define S_TOTAL   13294
#define TOKENS    (BATCH * S_TOTAL)     // 26588
#define D_MODEL   256
#define D_FC      1024
#define N_HEADS   8
#define N_LEVELS  4
#define N_POINTS  4
#define D_HEAD    32

__device__ __constant__ int c_H[4]     = {100, 50, 25, 13};
__device__ __constant__ int c_W[4]     = {100, 50, 25, 13};
__device__ __constant__ int c_start[4] = {0, 10000, 12500, 13125};

// ---------------- scratch (no cudaMalloc allowed) ----------------
__device__ float g_q     [TOKENS * D_MODEL];   // src + pos
__device__ float g_val   [TOKENS * D_MODEL];   // value projection
__device__ float g_off   [TOKENS * 256];       // offset projection
__device__ float g_attn  [TOKENS * 128];       // attention logits -> softmax
__device__ float g_samp  [TOKENS * D_MODEL];   // deform-attn sampled output
__device__ float g_attno [TOKENS * D_MODEL];   // after W_out
__device__ float g_x     [TOKENS * D_MODEL];   // after LN1
__device__ float g_h     [TOKENS * D_FC];      // ffn hidden
__device__ float g_ffn   [TOKENS * D_MODEL];   // ffn out

// ---------------- elementwise add ----------------
__global__ void add_kernel(const float* __restrict__ a, const float* __restrict__ b,
                           float* __restrict__ out, int n) {
    int i = blockIdx.x * blockDim.x + threadIdx.x;
    if (i < n) out[i] = a[i] + b[i];
}

// ---------------- fp32 tiled GEMM: C[M,N] = A[M,K] @ B[K,N] + bias ----------------
// BM=BN=64, BK=16, 256 threads, 4x4 microtile. N,K multiples of 16/64; M guarded.
template<bool RELU>
__global__ void gemm_bias(const float* __restrict__ A, const float* __restrict__ B,
                          const float* __restrict__ bias, float* __restrict__ C,
                          int M, int N, int K) {
    __shared__ float As[16][65];
    __shared__ float Bs[16][64];
    const int tx = threadIdx.x & 15;
    const int ty = threadIdx.x >> 4;
    const int row0 = blockIdx.y * 64;
    const int col0 = blockIdx.x * 64;

    float acc[4][4] = {};

    for (int k0 = 0; k0 < K; k0 += 16) {
        #pragma unroll
        for (int i = 0; i < 4; i++) {
            int idx = threadIdx.x + i * 256;      // 0..1023
            int r  = idx >> 4;                    // 0..63
            int kk = idx & 15;
            int gr = row0 + r;
            As[kk][r] = (gr < M) ? A[(size_t)gr * K + k0 + kk] : 0.f;
        }
        #pragma unroll
        for (int i = 0; i < 4; i++) {
            int idx = threadIdx.x + i * 256;
            int kk = idx >> 6;                    // 0..15
            int cc = idx & 63;
            Bs[kk][cc] = B[(size_t)(k0 + kk) * N + col0 + cc];
        }
        __syncthreads();
        #pragma unroll
        for (int kk = 0; kk < 16; kk++) {
            float a[4], bv[4];
            #pragma unroll
            for (int i = 0; i < 4; i++) a[i]  = As[kk][ty * 4 + i];
            #pragma unroll
            for (int j = 0; j < 4; j++) bv[j] = Bs[kk][tx * 4 + j];
            #pragma unroll
            for (int i = 0; i < 4; i++)
                #pragma unroll
                for (int j = 0; j < 4; j++)
                    acc[i][j] += a[i] * bv[j];
        }
        __syncthreads();
    }

    #pragma unroll
    for (int i = 0; i < 4; i++) {
        int gr = row0 + ty * 4 + i;
        if (gr >= M) continue;
        #pragma unroll
        for (int j = 0; j < 4; j++) {
            int gc = col0 + tx * 4 + j;
            float v = acc[i][j] + bias[gc];
            if (RELU) v = fmaxf(v, 0.f);
            C[(size_t)gr * N + gc] = v;
        }
    }
}

// ---------------- softmax over 16 (levels*points) per (token,head) ----------------
__global__ void softmax16(float* __restrict__ attn, int n) {
    int i = blockIdx.x * blockDim.x + threadIdx.x;
    if (i >= n) return;
    float* p = attn + (size_t)i * 16;
    float v[16];
    float m = -1e30f;
    #pragma unroll
    for (int j = 0; j < 16; j++) { v[j] = p[j]; m = fmaxf(m, v[j]); }
    float s = 0.f;
    #pragma unroll
    for (int j = 0; j < 16; j++) { v[j] = __expf(v[j] - m); s += v[j]; }
    float inv = 1.f / s;
    #pragma unroll
    for (int j = 0; j < 16; j++) p[j] = v[j] * inv;
}

// ---------------- multi-scale deformable sampling ----------------
// one block per token; warp = head; lane = channel
__global__ void ms_sample(const float* __restrict__ val, const float* __restrict__ off,
                          const float* __restrict__ attn, const float* __restrict__ ref,
                          float* __restrict__ out) {
    int token = blockIdx.x;
    int b = token / S_TOTAL;
    int h = threadIdx.x >> 5;
    int c = threadIdx.x & 31;

    const float* refp  = ref  + (size_t)token * (N_LEVELS * 2);
    const float* offp  = off  + (size_t)token * 256 + h * 32;
    const float* attnp = attn + (size_t)token * 128 + h * 16;
    const float* vbase = val  + (size_t)b * S_TOTAL * D_MODEL + h * D_HEAD + c;

    float acc = 0.f;
    #pragma unroll
    for (int l = 0; l < N_LEVELS; l++) {
        const int Hl = c_H[l], Wl = c_W[l];
        const float fH = (float)Hl, fW = (float)Wl;
        const float rx = refp[l * 2 + 0];
        const float ry = refp[l * 2 + 1];
        const float* vlev = vbase + (size_t)c_start[l] * D_MODEL;
        #pragma unroll
        for (int p = 0; p < N_POINTS; p++) {
            float ox = offp[l * 8 + p * 2 + 0];
            float oy = offp[l * 8 + p * 2 + 1];
            float px = (rx + ox / fW) * fW - 0.5f;
            float py = (ry + oy / fH) * fH - 0.5f;
            float x0 = floorf(px), y0 = floorf(py);
            float wx = px - x0, wy = py - y0;
            int x0i = (int)x0, y0i = (int)y0;
            float a = attnp[l * 4 + p];

            float s = 0.f;
            {   // (x0, y0)
                int xi = x0i, yi = y0i;
                if (xi >= 0 && xi < Wl && yi >= 0 && yi < Hl)
                    s += (1.f - wx) * (1.f - wy) * vlev[(size_t)(yi * Wl + xi) * D_MODEL];
            }
            {   // (x0+1, y0)
                int xi = x0i + 1, yi = y0i;
                if (xi >= 0 && xi < Wl && yi >= 0 && yi < Hl)
                    s += wx * (1.f - wy) * vlev[(size_t)(yi * Wl + xi) * D_MODEL];
            }
            {   // (x0, y0+1)
                int xi = x0i, yi = y0i + 1;
                if (xi >= 0 && xi < Wl && yi >= 0 && yi < Hl)
                    s += (1.f - wx) * wy * vlev[(size_t)(yi * Wl + xi) * D_MODEL];
            }
            {   // (x0+1, y0+1)
                int xi = x0i + 1, yi = y0i + 1;
                if (xi >= 0 && xi < Wl && yi >= 0 && yi < Hl)
                    s += wx * wy * vlev[(size_t)(yi * Wl + xi) * D_MODEL];
            }
            acc += a * s;
        }
    }
    out[(size_t)token * D_MODEL + h * D_HEAD + c] = acc;
}

// ---------------- residual add + LayerNorm (256 channels, 1 block/token) ----------------
__global__ void add_layernorm(const float* __restrict__ a, const float* __restrict__ b,
                              const float* __restrict__ gamma, const float* __restrict__ beta,
                              float* __restrict__ out) {
    __shared__ float red[8];
    int token = blockIdx.x;
    int c = threadIdx.x;
    float v = a[(size_t)token * D_MODEL + c] + b[(size_t)token * D_MODEL + c];

    // sum
    float s = v;
    #pragma unroll
    for (int o = 16; o > 0; o >>= 1) s += __shfl_xor_sync(0xffffffffu, s, o);
    if ((c & 31) == 0) red[c >> 5] = s;
    __syncthreads();
    if (c < 8) {
        float t = red[c];
        #pragma unroll
        for (int o = 4; o > 0; o >>= 1) t += __shfl_xor_sync(0xffu, t, o);
        if (c == 0) red[0] = t;
    }
    __syncthreads();
    float mu = red[0] * (1.f / D_MODEL);
    __syncthreads();

    // var
    float d = v - mu;
    float ss = d * d;
    #pragma unroll
    for (int o = 16; o > 0; o >>= 1) ss += __shfl_xor_sync(0xffffffffu, ss, o);
    if ((c & 31) == 0) red[c >> 5] = ss;
    __syncthreads();
    if (c < 8) {
        float t = red[c];
        #pragma unroll
        for (int o = 4; o > 0; o >>= 1) t += __shfl_xor_sync(0xffu, t, o);
        if (c == 0) red[0] = t;
    }
    __syncthreads();
    float var = red[0] * (1.f / D_MODEL);
    float inv = rsqrtf(var + 1e-5f);

    out[(size_t)token * D_MODEL + c] = d * inv * gamma[c] + beta[c];
}

// ---------------- launch ----------------
extern "C" void kernel_launch(void* const* d_in, const int* in_sizes, int n_in,
                              void* d_out, int out_size) {
    const float* src   = (const float*)d_in[0];
    const float* pos   = (const float*)d_in[1];
    const float* ref   = (const float*)d_in[2];
    // d_in[3] spatial_shapes (int64)  -- compile-time constants
    // d_in[4] level_start_index       -- compile-time constants
    const float* W_off = (const float*)d_in[5];
    const float* b_off = (const float*)d_in[6];
    const float* W_att = (const float*)d_in[7];
    const float* b_att = (const float*)d_in[8];
    const float* W_val = (const float*)d_in[9];
    const float* b_val = (const float*)d_in[10];
    const float* W_out = (const float*)d_in[11];
    const float* b_out = (const float*)d_in[12];
    const float* ln1g  = (const float*)d_in[13];
    const float* ln1b  = (const float*)d_in[14];
    const float* W1    = (const float*)d_in[15];
    const float* b1    = (const float*)d_in[16];
    const float* W2    = (const float*)d_in[17];
    const float* b2    = (const float*)d_in[18];
    const float* ln2g  = (const float*)d_in[19];
    const float* ln2b  = (const float*)d_in[20];
    float* out = (float*)d_out;

    float *q, *val, *off, *attn, *samp, *attno, *x, *h, *ffn;
    cudaGetSymbolAddress((void**)&q,     g_q);
    cudaGetSymbolAddress((void**)&val,   g_val);
    cudaGetSymbolAddress((void**)&off,   g_off);
    cudaGetSymbolAddress((void**)&attn,  g_attn);
    cudaGetSymbolAddress((void**)&samp,  g_samp);
    cudaGetSymbolAddress((void**)&attno, g_attno);
    cudaGetSymbolAddress((void**)&x,     g_x);
    cudaGetSymbolAddress((void**)&h,     g_h);
    cudaGetSymbolAddress((void**)&ffn,   g_ffn);

    const int M = TOKENS;
    dim3 thr(256);

    // q = src + pos
    add_kernel<<<(M * D_MODEL + 255) / 256, thr>>>(src, pos, q, M * D_MODEL);

    // projections
    {   dim3 grid(D_MODEL / 64, (M + 63) / 64);
        gemm_bias<false><<<grid, thr>>>(src, W_val, b_val, val, M, D_MODEL, D_MODEL); }
    {   dim3 grid(256 / 64, (M + 63) / 64);
        gemm_bias<false><<<grid, thr>>>(q, W_off, b_off, off, M, 256, D_MODEL); }
    {   dim3 grid(128 / 64, (M + 63) / 64);
        gemm_bias<false><<<grid, thr>>>(q, W_att, b_att, attn, M, 128, D_MODEL); }

    // softmax over 16 per (token, head)
    softmax16<<<(M * N_HEADS + 255) / 256, thr>>>(attn, M * N_HEADS);

    // deformable sampling
    ms_sample<<<M, thr>>>(val, off, attn, ref, samp);

    // output projection
    {   dim3 grid(D_MODEL / 64, (M + 63) / 64);
        gemm_bias<false><<<grid, thr>>>(samp, W_out, b_out, attno, M, D_MODEL, D_MODEL); }

    // x = LN(src + attn_out)
    add_layernorm<<<M, thr>>>(src, attno, ln1g, ln1b, x);

    // FFN
    {   dim3 grid(D_FC / 64, (M + 63) / 64);
        gemm_bias<true><<<grid, thr>>>(x, W1, b1, h, M, D_FC, D_MODEL); }
    {   dim3 grid(D_MODEL / 64, (M + 63) / 64);
        gemm_bias<false><<<grid, thr>>>(h, W2, b2, ffn, M, D_MODEL, D_FC); }

    // out = LN(x + ffn)
    add_layernorm<<<M, thr>>>(x, ffn, ln2g, ln2b, out);
}

// round 4
// speedup vs baseline: 1.9245x; 1.9245x over previous
#include <cuda_runtime.h>
#include <cuda_bf16.h>
#include <cstdint>
#include <math.h>

// ---------------- static problem shape ----------------
#define BATCH     2
#define S_TOTAL   13294
#define TOKENS    (BATCH * S_TOTAL)     // 26588
#define D_MODEL   256
#define D_FC      1024
#define N_HEADS   8
#define N_LEVELS  4
#define N_POINTS  4
#define D_HEAD    32

__device__ __constant__ int c_H[4]     = {100, 50, 25, 13};
__device__ __constant__ int c_W[4]     = {100, 50, 25, 13};
__device__ __constant__ int c_start[4] = {0, 10000, 12500, 13125};

// ---------------- scratch (no cudaMalloc allowed) ----------------
__device__ float g_q     [TOKENS * D_MODEL];
__device__ float g_val   [TOKENS * D_MODEL];
__device__ float g_off   [TOKENS * 256];
__device__ float g_attn  [TOKENS * 128];
__device__ float g_samp  [TOKENS * D_MODEL];
__device__ float g_attno [TOKENS * D_MODEL];
__device__ float g_x     [TOKENS * D_MODEL];
__device__ float g_h     [TOKENS * D_FC];
__device__ float g_ffn   [TOKENS * D_MODEL];

// ---------------- elementwise add (vectorized) ----------------
__global__ void add_kernel(const float4* __restrict__ a, const float4* __restrict__ b,
                           float4* __restrict__ out, int n4) {
    int i = blockIdx.x * blockDim.x + threadIdx.x;
    if (i < n4) {
        float4 x = a[i], y = b[i];
        out[i] = make_float4(x.x + y.x, x.y + y.y, x.z + y.z, x.w + y.w);
    }
}

// ---------------- tf32 helpers ----------------
__device__ __forceinline__ uint32_t f2tf32(float f) {
    uint32_t r;
    asm("cvt.rna.tf32.f32 %0, %1;" : "=r"(r) : "f"(f));
    return r;
}

__device__ __forceinline__ void mma_tf32(float& d0, float& d1, float& d2, float& d3,
                                         uint32_t a0, uint32_t a1, uint32_t a2, uint32_t a3,
                                         uint32_t b0, uint32_t b1) {
    asm volatile(
        "mma.sync.aligned.m16n8k8.row.col.f32.tf32.tf32.f32 "
        "{%0,%1,%2,%3}, {%4,%5,%6,%7}, {%8,%9}, {%0,%1,%2,%3};\n"
        : "+f"(d0), "+f"(d1), "+f"(d2), "+f"(d3)
        : "r"(a0), "r"(a1), "r"(a2), "r"(a3), "r"(b0), "r"(b1));
}

// ---------------- tf32 tensor-core GEMM ----------------
// C[M,N] = A[M,K] @ B[K,N] + bias (+ReLU).  BM=128, BN=64, BK=32, 256 thr (8 warps),
// warp tile 32x32 (2 m16 tiles x 4 n8 tiles), m16n8k8 mma, reg-prefetch double buffer.
// A smem: word idx(m,k) = m*32 + (k ^ ((m&7)<<2))  -> conflict-free STS.128 + frag LDS
// B smem: [k][n] with ld=72                        -> conflict-free STS.128 + frag LDS
#define GA_IDX(m, k) ((m) * 32 + ((k) ^ (((m) & 7) << 2)))

template<bool RELU>
__global__ void __launch_bounds__(256) gemm_tf32(
        const float* __restrict__ A, const float* __restrict__ B,
        const float* __restrict__ bias, float* __restrict__ C,
        int M, int N, int K) {
    __shared__ uint32_t As[128 * 32];   // 16 KB
    __shared__ uint32_t Bs[32 * 72];    // 9.2 KB

    const int tid  = threadIdx.x;
    const int lane = tid & 31;
    const int warp = tid >> 5;
    const int wm   = warp & 3;          // 4 warps along M
    const int wn   = warp >> 2;         // 2 warps along N
    const int row0 = blockIdx.y * 128;
    const int col0 = blockIdx.x * 64;

    // global load coordinates
    const int a_kv = tid & 7;           // float4 index along K (0..7)
    const int a_m0 = tid >> 3;          // row within tile (0..31), +32*i
    const int b_nv = tid & 15;          // float4 index along N (0..15)
    const int b_k0 = tid >> 4;          // k row (0..15), +16*i

    float acc[2][4][4];
    #pragma unroll
    for (int t = 0; t < 2; t++)
        #pragma unroll
        for (int n = 0; n < 4; n++)
            #pragma unroll
            for (int j = 0; j < 4; j++) acc[t][n][j] = 0.f;

    const int ntiles = K / 32;

    // ---- load tile 0 ----
    {
        #pragma unroll
        for (int i = 0; i < 4; i++) {
            int m = a_m0 + 32 * i;
            int gr = row0 + m;
            float4 v = (gr < M) ? *(const float4*)&A[(size_t)gr * K + a_kv * 4]
                                : make_float4(0.f, 0.f, 0.f, 0.f);
            uint32_t* dst = &As[GA_IDX(m, a_kv * 4)];
            dst[0] = f2tf32(v.x); dst[1] = f2tf32(v.y);
            dst[2] = f2tf32(v.z); dst[3] = f2tf32(v.w);
        }
        #pragma unroll
        for (int i = 0; i < 2; i++) {
            int k = b_k0 + 16 * i;
            float4 v = *(const float4*)&B[(size_t)k * N + col0 + b_nv * 4];
            uint32_t* dst = &Bs[k * 72 + b_nv * 4];
            dst[0] = f2tf32(v.x); dst[1] = f2tf32(v.y);
            dst[2] = f2tf32(v.z); dst[3] = f2tf32(v.w);
        }
    }
    __syncthreads();

    float4 pa[4], pb[2];
    for (int kt = 1; kt <= ntiles; kt++) {
        const bool have_next = (kt < ntiles);
        if (have_next) {
            const int kg = kt * 32;
            #pragma unroll
            for (int i = 0; i < 4; i++) {
                int gr = row0 + a_m0 + 32 * i;
                pa[i] = (gr < M) ? *(const float4*)&A[(size_t)gr * K + kg + a_kv * 4]
                                 : make_float4(0.f, 0.f, 0.f, 0.f);
            }
            #pragma unroll
            for (int i = 0; i < 2; i++) {
                int k = kg + b_k0 + 16 * i;
                pb[i] = *(const float4*)&B[(size_t)k * N + col0 + b_nv * 4];
            }
        }

        // ---- compute on current tile ----
        #pragma unroll
        for (int ks = 0; ks < 4; ks++) {
            const int kk = ks * 8 + (lane & 3);
            uint32_t af[2][4];
            #pragma unroll
            for (int t = 0; t < 2; t++) {
                int m = wm * 32 + t * 16 + (lane >> 2);
                af[t][0] = As[GA_IDX(m,     kk)];
                af[t][1] = As[GA_IDX(m + 8, kk)];
                af[t][2] = As[GA_IDX(m,     kk + 4)];
                af[t][3] = As[GA_IDX(m + 8, kk + 4)];
            }
            uint32_t bf[4][2];
            #pragma unroll
            for (int n = 0; n < 4; n++) {
                int nn = wn * 32 + n * 8 + (lane >> 2);
                bf[n][0] = Bs[kk * 72 + nn];
                bf[n][1] = Bs[(kk + 4) * 72 + nn];
            }
            #pragma unroll
            for (int t = 0; t < 2; t++)
                #pragma unroll
                for (int n = 0; n < 4; n++)
                    mma_tf32(acc[t][n][0], acc[t][n][1], acc[t][n][2], acc[t][n][3],
                             af[t][0], af[t][1], af[t][2], af[t][3],
                             bf[n][0], bf[n][1]);
        }
        __syncthreads();

        if (have_next) {
            #pragma unroll
            for (int i = 0; i < 4; i++) {
                int m = a_m0 + 32 * i;
                uint32_t* dst = &As[GA_IDX(m, a_kv * 4)];
                dst[0] = f2tf32(pa[i].x); dst[1] = f2tf32(pa[i].y);
                dst[2] = f2tf32(pa[i].z); dst[3] = f2tf32(pa[i].w);
            }
            #pragma unroll
            for (int i = 0; i < 2; i++) {
                int k = b_k0 + 16 * i;
                uint32_t* dst = &Bs[k * 72 + b_nv * 4];
                dst[0] = f2tf32(pb[i].x); dst[1] = f2tf32(pb[i].y);
                dst[2] = f2tf32(pb[i].z); dst[3] = f2tf32(pb[i].w);
            }
            __syncthreads();
        }
    }

    // ---- epilogue: bias (+relu) ----
    #pragma unroll
    for (int t = 0; t < 2; t++) {
        #pragma unroll
        for (int n = 0; n < 4; n++) {
            int gr = row0 + wm * 32 + t * 16 + (lane >> 2);
            int gc = col0 + wn * 32 + n * 8 + 2 * (lane & 3);
            float b0 = bias[gc], b1 = bias[gc + 1];
            if (gr < M) {
                float v0 = acc[t][n][0] + b0;
                float v1 = acc[t][n][1] + b1;
                if (RELU) { v0 = fmaxf(v0, 0.f); v1 = fmaxf(v1, 0.f); }
                C[(size_t)gr * N + gc]     = v0;
                C[(size_t)gr * N + gc + 1] = v1;
            }
            if (gr + 8 < M) {
                float v2 = acc[t][n][2] + b0;
                float v3 = acc[t][n][3] + b1;
                if (RELU) { v2 = fmaxf(v2, 0.f); v3 = fmaxf(v3, 0.f); }
                C[(size_t)(gr + 8) * N + gc]     = v2;
                C[(size_t)(gr + 8) * N + gc + 1] = v3;
            }
        }
    }
}

// ---------------- softmax over 16 per (token,head) ----------------
__global__ void softmax16(float* __restrict__ attn, int n) {
    int i = blockIdx.x * blockDim.x + threadIdx.x;
    if (i >= n) return;
    float4* p = (float4*)(attn + (size_t)i * 16);
    float4 r[4];
    float v[16];
    #pragma unroll
    for (int j = 0; j < 4; j++) r[j] = p[j];
    v[0]=r[0].x; v[1]=r[0].y; v[2]=r[0].z; v[3]=r[0].w;
    v[4]=r[1].x; v[5]=r[1].y; v[6]=r[1].z; v[7]=r[1].w;
    v[8]=r[2].x; v[9]=r[2].y; v[10]=r[2].z; v[11]=r[2].w;
    v[12]=r[3].x; v[13]=r[3].y; v[14]=r[3].z; v[15]=r[3].w;
    float m = -1e30f;
    #pragma unroll
    for (int j = 0; j < 16; j++) m = fmaxf(m, v[j]);
    float s = 0.f;
    #pragma unroll
    for (int j = 0; j < 16; j++) { v[j] = __expf(v[j] - m); s += v[j]; }
    float inv = 1.f / s;
    #pragma unroll
    for (int j = 0; j < 16; j++) v[j] *= inv;
    p[0] = make_float4(v[0], v[1], v[2], v[3]);
    p[1] = make_float4(v[4], v[5], v[6], v[7]);
    p[2] = make_float4(v[8], v[9], v[10], v[11]);
    p[3] = make_float4(v[12], v[13], v[14], v[15]);
}

// ---------------- multi-scale deformable sampling ----------------
__global__ void ms_sample(const float* __restrict__ val, const float* __restrict__ off,
                          const float* __restrict__ attn, const float* __restrict__ ref,
                          float* __restrict__ out) {
    int token = blockIdx.x;
    int b = token / S_TOTAL;
    int h = threadIdx.x >> 5;
    int c = threadIdx.x & 31;

    const float* refp  = ref  + (size_t)token * (N_LEVELS * 2);
    const float* offp  = off  + (size_t)token * 256 + h * 32;
    const float* attnp = attn + (size_t)token * 128 + h * 16;
    const float* vbase = val  + (size_t)b * S_TOTAL * D_MODEL + h * D_HEAD + c;

    float acc = 0.f;
    #pragma unroll
    for (int l = 0; l < N_LEVELS; l++) {
        const int Hl = c_H[l], Wl = c_W[l];
        const float fH = (float)Hl, fW = (float)Wl;
        const float rx = refp[l * 2 + 0];
        const float ry = refp[l * 2 + 1];
        const float* vlev = vbase + (size_t)c_start[l] * D_MODEL;
        #pragma unroll
        for (int p = 0; p < N_POINTS; p++) {
            float ox = offp[l * 8 + p * 2 + 0];
            float oy = offp[l * 8 + p * 2 + 1];
            float px = (rx + ox / fW) * fW - 0.5f;
            float py = (ry + oy / fH) * fH - 0.5f;
            float x0 = floorf(px), y0 = floorf(py);
            float wx = px - x0, wy = py - y0;
            int x0i = (int)x0, y0i = (int)y0;
            float a = attnp[l * 4 + p];

            float s = 0.f;
            {
                int xi = x0i, yi = y0i;
                if (xi >= 0 && xi < Wl && yi >= 0 && yi < Hl)
                    s += (1.f - wx) * (1.f - wy) * vlev[(size_t)(yi * Wl + xi) * D_MODEL];
            }
            {
                int xi = x0i + 1, yi = y0i;
                if (xi >= 0 && xi < Wl && yi >= 0 && yi < Hl)
                    s += wx * (1.f - wy) * vlev[(size_t)(yi * Wl + xi) * D_MODEL];
            }
            {
                int xi = x0i, yi = y0i + 1;
                if (xi >= 0 && xi < Wl && yi >= 0 && yi < Hl)
                    s += (1.f - wx) * wy * vlev[(size_t)(yi * Wl + xi) * D_MODEL];
            }
            {
                int xi = x0i + 1, yi = y0i + 1;
                if (xi >= 0 && xi < Wl && yi >= 0 && yi < Hl)
                    s += wx * wy * vlev[(size_t)(yi * Wl + xi) * D_MODEL];
            }
            acc += a * s;
        }
    }
    out[(size_t)token * D_MODEL + h * D_HEAD + c] = acc;
}

// ---------------- residual add + LayerNorm ----------------
__global__ void add_layernorm(const float* __restrict__ a, const float* __restrict__ b,
                              const float* __restrict__ gamma, const float* __restrict__ beta,
                              float* __restrict__ out) {
    __shared__ float red[8];
    int token = blockIdx.x;
    int c = threadIdx.x;
    float v = a[(size_t)token * D_MODEL + c] + b[(size_t)token * D_MODEL + c];

    float s = v;
    #pragma unroll
    for (int o = 16; o > 0; o >>= 1) s += __shfl_xor_sync(0xffffffffu, s, o);
    if ((c & 31) == 0) red[c >> 5] = s;
    __syncthreads();
    if (c < 8) {
        float t = red[c];
        #pragma unroll
        for (int o = 4; o > 0; o >>= 1) t += __shfl_xor_sync(0xffu, t, o);
        if (c == 0) red[0] = t;
    }
    __syncthreads();
    float mu = red[0] * (1.f / D_MODEL);
    __syncthreads();

    float d = v - mu;
    float ss = d * d;
    #pragma unroll
    for (int o = 16; o > 0; o >>= 1) ss += __shfl_xor_sync(0xffffffffu, ss, o);
    if ((c & 31) == 0) red[c >> 5] = ss;
    __syncthreads();
    if (c < 8) {
        float t = red[c];
        #pragma unroll
        for (int o = 4; o > 0; o >>= 1) t += __shfl_xor_sync(0xffu, t, o);
        if (c == 0) red[0] = t;
    }
    __syncthreads();
    float var = red[0] * (1.f / D_MODEL);
    float inv = rsqrtf(var + 1e-5f);

    out[(size_t)token * D_MODEL + c] = d * inv * gamma[c] + beta[c];
}

// ---------------- launch ----------------
extern "C" void kernel_launch(void* const* d_in, const int* in_sizes, int n_in,
                              void* d_out, int out_size) {
    const float* src   = (const float*)d_in[0];
    const float* pos   = (const float*)d_in[1];
    const float* ref   = (const float*)d_in[2];
    const float* W_off = (const float*)d_in[5];
    const float* b_off = (const float*)d_in[6];
    const float* W_att = (const float*)d_in[7];
    const float* b_att = (const float*)d_in[8];
    const float* W_val = (const float*)d_in[9];
    const float* b_val = (const float*)d_in[10];
    const float* W_out = (const float*)d_in[11];
    const float* b_out = (const float*)d_in[12];
    const float* ln1g  = (const float*)d_in[13];
    const float* ln1b  = (const float*)d_in[14];
    const float* W1    = (const float*)d_in[15];
    const float* b1    = (const float*)d_in[16];
    const float* W2    = (const float*)d_in[17];
    const float* b2    = (const float*)d_in[18];
    const float* ln2g  = (const float*)d_in[19];
    const float* ln2b  = (const float*)d_in[20];
    float* out = (float*)d_out;

    float *q, *val, *off, *attn, *samp, *attno, *x, *h, *ffn;
    cudaGetSymbolAddress((void**)&q,     g_q);
    cudaGetSymbolAddress((void**)&val,   g_val);
    cudaGetSymbolAddress((void**)&off,   g_off);
    cudaGetSymbolAddress((void**)&attn,  g_attn);
    cudaGetSymbolAddress((void**)&samp,  g_samp);
    cudaGetSymbolAddress((void**)&attno, g_attno);
    cudaGetSymbolAddress((void**)&x,     g_x);
    cudaGetSymbolAddress((void**)&h,     g_h);
    cudaGetSymbolAddress((void**)&ffn,   g_ffn);

    const int M = TOKENS;
    const int MB = (M + 127) / 128;
    dim3 thr(256);

    // q = src + pos
    add_kernel<<<(M * D_MODEL / 4 + 255) / 256, thr>>>(
        (const float4*)src, (const float4*)pos, (float4*)q, M * D_MODEL / 4);

    // projections (tensor cores)
    gemm_tf32<false><<<dim3(D_MODEL / 64, MB), thr>>>(src, W_val, b_val, val, M, D_MODEL, D_MODEL);
    gemm_tf32<false><<<dim3(256 / 64,     MB), thr>>>(q,   W_off, b_off, off, M, 256,     D_MODEL);
    gemm_tf32<false><<<dim3(128 / 64,     MB), thr>>>(q,   W_att, b_att, attn, M, 128,    D_MODEL);

    softmax16<<<(M * N_HEADS + 255) / 256, thr>>>(attn, M * N_HEADS);

    ms_sample<<<M, thr>>>(val, off, attn, ref, samp);

    gemm_tf32<false><<<dim3(D_MODEL / 64, MB), thr>>>(samp, W_out, b_out, attno, M, D_MODEL, D_MODEL);

    add_layernorm<<<M, thr>>>(src, attno, ln1g, ln1b, x);

    gemm_tf32<true ><<<dim3(D_FC / 64,    MB), thr>>>(x, W1, b1, h,   M, D_FC,    D_MODEL);
    gemm_tf32<false><<<dim3(D_MODEL / 64, MB), thr>>>(h, W2, b2, ffn, M, D_MODEL, D_FC);

    add_layernorm<<<M, thr>>>(x, ffn, ln2g, ln2b, out);
}

// round 5
// speedup vs baseline: 2.2151x; 1.1510x over previous
#include <cuda_runtime.h>
#include <cuda_bf16.h>
#include <cstdint>
#include <math.h>

// ---------------- static problem shape ----------------
#define BATCH     2
#define S_TOTAL   13294
#define TOKENS    (BATCH * S_TOTAL)     // 26588
#define D_MODEL   256
#define D_FC      1024
#define N_HEADS   8
#define N_LEVELS  4
#define N_POINTS  4
#define D_HEAD    32

__device__ __constant__ int c_H[4]     = {100, 50, 25, 13};
__device__ __constant__ int c_W[4]     = {100, 50, 25, 13};
__device__ __constant__ int c_start[4] = {0, 10000, 12500, 13125};

// ---------------- scratch (no cudaMalloc allowed) ----------------
__device__ float g_q     [TOKENS * D_MODEL];
__device__ float g_val   [TOKENS * D_MODEL];
__device__ float g_off   [TOKENS * 256];
__device__ float g_attn  [TOKENS * 128];
__device__ float g_samp  [TOKENS * D_MODEL];
__device__ float g_attno [TOKENS * D_MODEL];
__device__ float g_x     [TOKENS * D_MODEL];
__device__ float g_h     [TOKENS * D_FC];
__device__ float g_ffn   [TOKENS * D_MODEL];
__device__ float g_srcr  [TOKENS * D_MODEL];   // tf32-rounded src
__device__ float g_wr    [753664];             // tf32-rounded weights

// weight offsets inside g_wr
#define WR_VAL  0
#define WR_OFF  65536
#define WR_ATT  131072
#define WR_OUT  163840
#define WR_W1   229376
#define WR_W2   491520

// ---------------- tf32 helpers ----------------
__device__ __forceinline__ uint32_t f2tf32(float f) {
    uint32_t r;
    asm("cvt.rna.tf32.f32 %0, %1;" : "=r"(r) : "f"(f));
    return r;
}
__device__ __forceinline__ float roundtf(float f) { return __uint_as_float(f2tf32(f)); }

__device__ __forceinline__ void mma_tf32(float& d0, float& d1, float& d2, float& d3,
                                         uint32_t a0, uint32_t a1, uint32_t a2, uint32_t a3,
                                         uint32_t b0, uint32_t b1) {
    asm volatile(
        "mma.sync.aligned.m16n8k8.row.col.f32.tf32.tf32.f32 "
        "{%0,%1,%2,%3}, {%4,%5,%6,%7}, {%8,%9}, {%0,%1,%2,%3};\n"
        : "+f"(d0), "+f"(d1), "+f"(d2), "+f"(d3)
        : "r"(a0), "r"(a1), "r"(a2), "r"(a3), "r"(b0), "r"(b1));
}

// ---------------- cp.async helpers ----------------
__device__ __forceinline__ void cp16(uint32_t smem_addr, const void* gmem, bool pred) {
    int sz = pred ? 16 : 0;
    asm volatile("cp.async.cg.shared.global [%0], [%1], 16, %2;\n"
                 :: "r"(smem_addr), "l"(gmem), "r"(sz));
}
__device__ __forceinline__ void cp_commit() {
    asm volatile("cp.async.commit_group;\n");
}

// ---------------- round-copy (tf32 RNA) ----------------
__global__ void round_copy4(const float4* __restrict__ in, float4* __restrict__ out, int n4) {
    int i = blockIdx.x * blockDim.x + threadIdx.x;
    if (i < n4) {
        float4 v = in[i];
        out[i] = make_float4(roundtf(v.x), roundtf(v.y), roundtf(v.z), roundtf(v.w));
    }
}

// ---------------- elementwise add (rounded output) ----------------
__global__ void add_round_kernel(const float4* __restrict__ a, const float4* __restrict__ b,
                                 float4* __restrict__ out, int n4) {
    int i = blockIdx.x * blockDim.x + threadIdx.x;
    if (i < n4) {
        float4 x = a[i], y = b[i];
        out[i] = make_float4(roundtf(x.x + y.x), roundtf(x.y + y.y),
                             roundtf(x.z + y.z), roundtf(x.w + y.w));
    }
}

// ---------------- tf32 tensor-core GEMM, cp.async 3-stage ----------------
// C[M,N] = A[M,K] @ B[K,N] + bias (+ReLU) (+tf32-round output).
// BM=128, BN=64, BK=32, 256 threads (8 warps), warp tile 32x32, m16n8k8.
// A smem: word idx(m,k) = m*32 + (k ^ ((m&7)<<2));  B smem: [k][n] ld=72.
// Operands arrive PRE-ROUNDED to tf32, so in-register truncation is exact.
#define GA_IDX(m, k) ((m) * 32 + ((k) ^ (((m) & 7) << 2)))
#define AS_WORDS 4096           // 128*32
#define BS_WORDS 2304           // 32*72
#define SMEM_BYTES ((3 * AS_WORDS + 3 * BS_WORDS) * 4)   // 76800

template<bool RELU, bool ROUND_OUT>
__global__ void __launch_bounds__(256) gemm_tf32(
        const float* __restrict__ A, const float* __restrict__ B,
        const float* __restrict__ bias, float* __restrict__ C,
        int M, int N, int K) {
    extern __shared__ uint32_t smem[];
    uint32_t* As = smem;                       // 3 stages of A
    uint32_t* Bs = smem + 3 * AS_WORDS;        // 3 stages of B
    const uint32_t sAs = (uint32_t)__cvta_generic_to_shared(As);
    const uint32_t sBs = (uint32_t)__cvta_generic_to_shared(Bs);

    const int tid  = threadIdx.x;
    const int lane = tid & 31;
    const int warp = tid >> 5;
    const int wm   = warp & 3;
    const int wn   = warp >> 2;
    const int row0 = blockIdx.y * 128;
    const int col0 = blockIdx.x * 64;

    const int a_kv = tid & 7;           // float4 idx along K
    const int a_m0 = tid >> 3;          // 0..31 (+32*i)
    const int b_nv = tid & 15;          // float4 idx along N
    const int b_k0 = tid >> 4;          // 0..15 (+16*i)

    const int ntiles = K / 32;

    // issue one k-tile's loads into stage st
    auto issue = [&](int kt, int st) {
        const int kg = kt * 32;
        const uint32_t aBase = sAs + st * (AS_WORDS * 4);
        const uint32_t bBase = sBs + st * (BS_WORDS * 4);
        #pragma unroll
        for (int i = 0; i < 4; i++) {
            int m = a_m0 + 32 * i;
            int gr = row0 + m;
            bool ok = gr < M;
            const float* g = A + (size_t)(ok ? gr : 0) * K + kg + a_kv * 4;
            cp16(aBase + GA_IDX(m, a_kv * 4) * 4, g, ok);
        }
        #pragma unroll
        for (int i = 0; i < 2; i++) {
            int k = b_k0 + 16 * i;
            const float* g = B + (size_t)(kg + k) * N + col0 + b_nv * 4;
            cp16(bBase + (k * 72 + b_nv * 4) * 4, g, true);
        }
        cp_commit();
    };

    float acc[2][4][4];
    #pragma unroll
    for (int t = 0; t < 2; t++)
        #pragma unroll
        for (int n = 0; n < 4; n++)
            #pragma unroll
            for (int j = 0; j < 4; j++) acc[t][n][j] = 0.f;

    // prologue: stages 0 and 1
    issue(0, 0);
    if (ntiles > 1) issue(1, 1);

    for (int kt = 0; kt < ntiles; kt++) {
        if (kt + 1 < ntiles) { asm volatile("cp.async.wait_group 1;\n"); }
        else                 { asm volatile("cp.async.wait_group 0;\n"); }
        __syncthreads();
        if (kt + 2 < ntiles) issue(kt + 2, (kt + 2) % 3);

        const int st = kt % 3;
        const uint32_t* Asb = As + st * AS_WORDS;
        const uint32_t* Bsb = Bs + st * BS_WORDS;

        #pragma unroll
        for (int ks = 0; ks < 4; ks++) {
            const int kk = ks * 8 + (lane & 3);
            uint32_t af[2][4];
            #pragma unroll
            for (int t = 0; t < 2; t++) {
                int m = wm * 32 + t * 16 + (lane >> 2);
                af[t][0] = Asb[GA_IDX(m,     kk)];
                af[t][1] = Asb[GA_IDX(m + 8, kk)];
                af[t][2] = Asb[GA_IDX(m,     kk + 4)];
                af[t][3] = Asb[GA_IDX(m + 8, kk + 4)];
            }
            uint32_t bf[4][2];
            #pragma unroll
            for (int n = 0; n < 4; n++) {
                int nn = wn * 32 + n * 8 + (lane >> 2);
                bf[n][0] = Bsb[kk * 72 + nn];
                bf[n][1] = Bsb[(kk + 4) * 72 + nn];
            }
            #pragma unroll
            for (int t = 0; t < 2; t++)
                #pragma unroll
                for (int n = 0; n < 4; n++)
                    mma_tf32(acc[t][n][0], acc[t][n][1], acc[t][n][2], acc[t][n][3],
                             af[t][0], af[t][1], af[t][2], af[t][3],
                             bf[n][0], bf[n][1]);
        }
        // no trailing barrier: stage st is only overwritten by the issue()
        // in iteration kt+1, which happens after that iteration's barrier.
    }

    // ---- epilogue ----
    #pragma unroll
    for (int t = 0; t < 2; t++) {
        #pragma unroll
        for (int n = 0; n < 4; n++) {
            int gr = row0 + wm * 32 + t * 16 + (lane >> 2);
            int gc = col0 + wn * 32 + n * 8 + 2 * (lane & 3);
            float b0 = bias[gc], b1 = bias[gc + 1];
            if (gr < M) {
                float v0 = acc[t][n][0] + b0;
                float v1 = acc[t][n][1] + b1;
                if (RELU) { v0 = fmaxf(v0, 0.f); v1 = fmaxf(v1, 0.f); }
                if (ROUND_OUT) { v0 = roundtf(v0); v1 = roundtf(v1); }
                C[(size_t)gr * N + gc]     = v0;
                C[(size_t)gr * N + gc + 1] = v1;
            }
            if (gr + 8 < M) {
                float v2 = acc[t][n][2] + b0;
                float v3 = acc[t][n][3] + b1;
                if (RELU) { v2 = fmaxf(v2, 0.f); v3 = fmaxf(v3, 0.f); }
                if (ROUND_OUT) { v2 = roundtf(v2); v3 = roundtf(v3); }
                C[(size_t)(gr + 8) * N + gc]     = v2;
                C[(size_t)(gr + 8) * N + gc + 1] = v3;
            }
        }
    }
}

// ---------------- softmax over 16 per (token,head) ----------------
__global__ void softmax16(float* __restrict__ attn, int n) {
    int i = blockIdx.x * blockDim.x + threadIdx.x;
    if (i >= n) return;
    float4* p = (float4*)(attn + (size_t)i * 16);
    float4 r[4];
    float v[16];
    #pragma unroll
    for (int j = 0; j < 4; j++) r[j] = p[j];
    v[0]=r[0].x; v[1]=r[0].y; v[2]=r[0].z; v[3]=r[0].w;
    v[4]=r[1].x; v[5]=r[1].y; v[6]=r[1].z; v[7]=r[1].w;
    v[8]=r[2].x; v[9]=r[2].y; v[10]=r[2].z; v[11]=r[2].w;
    v[12]=r[3].x; v[13]=r[3].y; v[14]=r[3].z; v[15]=r[3].w;
    float m = -1e30f;
    #pragma unroll
    for (int j = 0; j < 16; j++) m = fmaxf(m, v[j]);
    float s = 0.f;
    #pragma unroll
    for (int j = 0; j < 16; j++) { v[j] = __expf(v[j] - m); s += v[j]; }
    float inv = 1.f / s;
    #pragma unroll
    for (int j = 0; j < 16; j++) v[j] *= inv;
    p[0] = make_float4(v[0], v[1], v[2], v[3]);
    p[1] = make_float4(v[4], v[5], v[6], v[7]);
    p[2] = make_float4(v[8], v[9], v[10], v[11]);
    p[3] = make_float4(v[12], v[13], v[14], v[15]);
}

// ---------------- multi-scale deformable sampling (rounded output) ----------------
__global__ void ms_sample(const float* __restrict__ val, const float* __restrict__ off,
                          const float* __restrict__ attn, const float* __restrict__ ref,
                          float* __restrict__ out) {
    int token = blockIdx.x;
    int b = token / S_TOTAL;
    int h = threadIdx.x >> 5;
    int c = threadIdx.x & 31;

    const float* refp  = ref  + (size_t)token * (N_LEVELS * 2);
    const float* offp  = off  + (size_t)token * 256 + h * 32;
    const float* attnp = attn + (size_t)token * 128 + h * 16;
    const float* vbase = val  + (size_t)b * S_TOTAL * D_MODEL + h * D_HEAD + c;

    float acc = 0.f;
    #pragma unroll
    for (int l = 0; l < N_LEVELS; l++) {
        const int Hl = c_H[l], Wl = c_W[l];
        const float fH = (float)Hl, fW = (float)Wl;
        const float rx = refp[l * 2 + 0];
        const float ry = refp[l * 2 + 1];
        const float* vlev = vbase + (size_t)c_start[l] * D_MODEL;
        #pragma unroll
        for (int p = 0; p < N_POINTS; p++) {
            float ox = offp[l * 8 + p * 2 + 0];
            float oy = offp[l * 8 + p * 2 + 1];
            float px = (rx + ox / fW) * fW - 0.5f;
            float py = (ry + oy / fH) * fH - 0.5f;
            float x0 = floorf(px), y0 = floorf(py);
            float wx = px - x0, wy = py - y0;
            int x0i = (int)x0, y0i = (int)y0;
            float a = attnp[l * 4 + p];

            float s = 0.f;
            {
                int xi = x0i, yi = y0i;
                if (xi >= 0 && xi < Wl && yi >= 0 && yi < Hl)
                    s += (1.f - wx) * (1.f - wy) * vlev[(size_t)(yi * Wl + xi) * D_MODEL];
            }
            {
                int xi = x0i + 1, yi = y0i;
                if (xi >= 0 && xi < Wl && yi >= 0 && yi < Hl)
                    s += wx * (1.f - wy) * vlev[(size_t)(yi * Wl + xi) * D_MODEL];
            }
            {
                int xi = x0i, yi = y0i + 1;
                if (xi >= 0 && xi < Wl && yi >= 0 && yi < Hl)
                    s += (1.f - wx) * wy * vlev[(size_t)(yi * Wl + xi) * D_MODEL];
            }
            {
                int xi = x0i + 1, yi = y0i + 1;
                if (xi >= 0 && xi < Wl && yi >= 0 && yi < Hl)
                    s += wx * wy * vlev[(size_t)(yi * Wl + xi) * D_MODEL];
            }
            acc += a * s;
        }
    }
    out[(size_t)token * D_MODEL + h * D_HEAD + c] = roundtf(acc);
}

// ---------------- residual add + LayerNorm ----------------
template<bool RND>
__global__ void add_layernorm(const float* __restrict__ a, const float* __restrict__ b,
                              const float* __restrict__ gamma, const float* __restrict__ beta,
                              float* __restrict__ out) {
    __shared__ float red[8];
    int token = blockIdx.x;
    int c = threadIdx.x;
    float v = a[(size_t)token * D_MODEL + c] + b[(size_t)token * D_MODEL + c];

    float s = v;
    #pragma unroll
    for (int o = 16; o > 0; o >>= 1) s += __shfl_xor_sync(0xffffffffu, s, o);
    if ((c & 31) == 0) red[c >> 5] = s;
    __syncthreads();
    if (c < 8) {
        float t = red[c];
        #pragma unroll
        for (int o = 4; o > 0; o >>= 1) t += __shfl_xor_sync(0xffu, t, o);
        if (c == 0) red[0] = t;
    }
    __syncthreads();
    float mu = red[0] * (1.f / D_MODEL);
    __syncthreads();

    float d = v - mu;
    float ss = d * d;
    #pragma unroll
    for (int o = 16; o > 0; o >>= 1) ss += __shfl_xor_sync(0xffffffffu, ss, o);
    if ((c & 31) == 0) red[c >> 5] = ss;
    __syncthreads();
    if (c < 8) {
        float t = red[c];
        #pragma unroll
        for (int o = 4; o > 0; o >>= 1) t += __shfl_xor_sync(0xffu, t, o);
        if (c == 0) red[0] = t;
    }
    __syncthreads();
    float var = red[0] * (1.f / D_MODEL);
    float inv = rsqrtf(var + 1e-5f);

    float o_ = d * inv * gamma[c] + beta[c];
    out[(size_t)token * D_MODEL + c] = RND ? roundtf(o_) : o_;
}

// ---------------- launch ----------------
extern "C" void kernel_launch(void* const* d_in, const int* in_sizes, int n_in,
                              void* d_out, int out_size) {
    const float* src   = (const float*)d_in[0];
    const float* pos   = (const float*)d_in[1];
    const float* ref   = (const float*)d_in[2];
    const float* W_off = (const float*)d_in[5];
    const float* b_off = (const float*)d_in[6];
    const float* W_att = (const float*)d_in[7];
    const float* b_att = (const float*)d_in[8];
    const float* W_val = (const float*)d_in[9];
    const float* b_val = (const float*)d_in[10];
    const float* W_out = (const float*)d_in[11];
    const float* b_out = (const float*)d_in[12];
    const float* ln1g  = (const float*)d_in[13];
    const float* ln1b  = (const float*)d_in[14];
    const float* W1    = (const float*)d_in[15];
    const float* b1    = (const float*)d_in[16];
    const float* W2    = (const float*)d_in[17];
    const float* b2    = (const float*)d_in[18];
    const float* ln2g  = (const float*)d_in[19];
    const float* ln2b  = (const float*)d_in[20];
    float* out = (float*)d_out;

    float *q, *val, *off, *attn, *samp, *attno, *x, *h, *ffn, *srcr, *wr;
    cudaGetSymbolAddress((void**)&q,     g_q);
    cudaGetSymbolAddress((void**)&val,   g_val);
    cudaGetSymbolAddress((void**)&off,   g_off);
    cudaGetSymbolAddress((void**)&attn,  g_attn);
    cudaGetSymbolAddress((void**)&samp,  g_samp);
    cudaGetSymbolAddress((void**)&attno, g_attno);
    cudaGetSymbolAddress((void**)&x,     g_x);
    cudaGetSymbolAddress((void**)&h,     g_h);
    cudaGetSymbolAddress((void**)&ffn,   g_ffn);
    cudaGetSymbolAddress((void**)&srcr,  g_srcr);
    cudaGetSymbolAddress((void**)&wr,    g_wr);

    cudaFuncSetAttribute(gemm_tf32<false, false>,
                         cudaFuncAttributeMaxDynamicSharedMemorySize, SMEM_BYTES);
    cudaFuncSetAttribute(gemm_tf32<true, true>,
                         cudaFuncAttributeMaxDynamicSharedMemorySize, SMEM_BYTES);

    const int M = TOKENS;
    const int MB = (M + 127) / 128;
    dim3 thr(256);

    // pre-round weights + src to tf32 (RNA) so GEMM truncation is exact
    auto rc = [&](const float* in_, float* out_, int n) {
        round_copy4<<<(n / 4 + 255) / 256, thr>>>((const float4*)in_, (float4*)out_, n / 4);
    };
    rc(W_val, wr + WR_VAL, 65536);
    rc(W_off, wr + WR_OFF, 65536);
    rc(W_att, wr + WR_ATT, 32768);
    rc(W_out, wr + WR_OUT, 65536);
    rc(W1,    wr + WR_W1,  262144);
    rc(W2,    wr + WR_W2,  262144);
    rc(src,   srcr,        M * D_MODEL);

    // q = round(src + pos)
    add_round_kernel<<<(M * D_MODEL / 4 + 255) / 256, thr>>>(
        (const float4*)src, (const float4*)pos, (float4*)q, M * D_MODEL / 4);

    // projections (tensor cores, cp.async pipeline)
    gemm_tf32<false, false><<<dim3(D_MODEL / 64, MB), thr, SMEM_BYTES>>>(
        srcr, wr + WR_VAL, b_val, val, M, D_MODEL, D_MODEL);
    gemm_tf32<false, false><<<dim3(256 / 64, MB), thr, SMEM_BYTES>>>(
        q, wr + WR_OFF, b_off, off, M, 256, D_MODEL);
    gemm_tf32<false, false><<<dim3(128 / 64, MB), thr, SMEM_BYTES>>>(
        q, wr + WR_ATT, b_att, attn, M, 128, D_MODEL);

    softmax16<<<(M * N_HEADS + 255) / 256, thr>>>(attn, M * N_HEADS);

    ms_sample<<<M, thr>>>(val, off, attn, ref, samp);

    gemm_tf32<false, false><<<dim3(D_MODEL / 64, MB), thr, SMEM_BYTES>>>(
        samp, wr + WR_OUT, b_out, attno, M, D_MODEL, D_MODEL);

    add_layernorm<true><<<M, thr>>>(src, attno, ln1g, ln1b, x);

    gemm_tf32<true, true><<<dim3(D_FC / 64, MB), thr, SMEM_BYTES>>>(
        x, wr + WR_W1, b1, h, M, D_FC, D_MODEL);
    gemm_tf32<false, false><<<dim3(D_MODEL / 64, MB), thr, SMEM_BYTES>>>(
        h, wr + WR_W2, b2, ffn, M, D_MODEL, D_FC);

    add_layernorm<false><<<M, thr>>>(x, ffn, ln2g, ln2b, out);
}

// round 7
// speedup vs baseline: 2.5422x; 1.1477x over previous
#include <cuda_runtime.h>
#include <cuda_fp16.h>
#include <cstdint>
#include <math.h>

// ---------------- static problem shape ----------------
#define BATCH     2
#define S_TOTAL   13294
#define TOKENS    (BATCH * S_TOTAL)     // 26588
#define D_MODEL   256
#define D_FC      1024
#define N_HEADS   8
#define N_LEVELS  4
#define N_POINTS  4
#define D_HEAD    32

__device__ __constant__ int c_H[4]     = {100, 50, 25, 13};
__device__ __constant__ int c_W[4]     = {100, 50, 25, 13};
__device__ __constant__ int c_start[4] = {0, 10000, 12500, 13125};

// ---------------- scratch (no cudaMalloc allowed) ----------------
__device__ float  g_val    [TOKENS * D_MODEL];   // value projection (fp32)
__device__ float  g_oa     [TOKENS * 384];       // fused [off(256) | attn(128)]
__device__ float  g_attno  [TOKENS * D_MODEL];
__device__ float  g_x      [TOKENS * D_MODEL];
__device__ float  g_ffn    [TOKENS * D_MODEL];
__device__ __half g_srch   [TOKENS * D_MODEL];   // fp16 src
__device__ __half g_qh     [TOKENS * D_MODEL];   // fp16 q = src+pos
__device__ __half g_samph  [TOKENS * D_MODEL];   // fp16 sampled
__device__ __half g_xh     [TOKENS * D_MODEL];   // fp16 LN1 out
__device__ __half g_hh     [TOKENS * D_FC];      // fp16 ffn hidden
__device__ __half g_wt     [753664];             // fp16 transposed weights [N][K]
__device__ float  g_boa    [384];                // concat bias off|attn

// offsets in g_wt (halves)
#define WT_VAL 0
#define WT_OA  65536          // 384 x 256
#define WT_OUT 163840         // 256 x 256
#define WT_W1  229376         // 1024 x 256
#define WT_W2  491520         // 256 x 1024

// ---------------- mma fp16 helper ----------------
__device__ __forceinline__ void mma_f16(float& d0, float& d1, float& d2, float& d3,
                                        uint32_t a0, uint32_t a1, uint32_t a2, uint32_t a3,
                                        uint32_t b0, uint32_t b1) {
    asm volatile(
        "mma.sync.aligned.m16n8k16.row.col.f32.f16.f16.f32 "
        "{%0,%1,%2,%3}, {%4,%5,%6,%7}, {%8,%9}, {%0,%1,%2,%3};\n"
        : "+f"(d0), "+f"(d1), "+f"(d2), "+f"(d3)
        : "r"(a0), "r"(a1), "r"(a2), "r"(a3), "r"(b0), "r"(b1));
}

// ---------------- cp.async helpers ----------------
__device__ __forceinline__ void cp16(uint32_t smem_addr, const void* gmem, bool pred) {
    int sz = pred ? 16 : 0;
    asm volatile("cp.async.cg.shared.global [%0], [%1], 16, %2;\n"
                 :: "r"(smem_addr), "l"(gmem), "r"(sz));
}
__device__ __forceinline__ void cp_commit() {
    asm volatile("cp.async.commit_group;\n");
}

// ---------------- weight transpose + fp16 convert ----------------
// in: fp32 [K][N] row-major; out: fp16 [N][K] (row n at rowOff+n)
__global__ void convT(const float* __restrict__ in, __half* __restrict__ out,
                      int K, int N, int rowOff) {
    __shared__ float t[32][33];
    int k0 = blockIdx.y * 32, n0 = blockIdx.x * 32;
    int tx = threadIdx.x & 31, ty = threadIdx.x >> 5;   // 256 threads
    #pragma unroll
    for (int i = 0; i < 32; i += 8)
        t[ty + i][tx] = in[(size_t)(k0 + ty + i) * N + n0 + tx];
    __syncthreads();
    #pragma unroll
    for (int i = 0; i < 32; i += 8)
        out[(size_t)(rowOff + n0 + ty + i) * K + k0 + tx] = __float2half(t[tx][ty + i]);
}

// ---------------- fp32 -> fp16 convert ----------------
__global__ void conv_h4(const float4* __restrict__ in, __half2* __restrict__ out, int n4) {
    int i = blockIdx.x * blockDim.x + threadIdx.x;
    if (i < n4) {
        float4 v = in[i];
        out[2 * i]     = __floats2half2_rn(v.x, v.y);
        out[2 * i + 1] = __floats2half2_rn(v.z, v.w);
    }
}

// ---------------- q = fp16(src + pos) ----------------
__global__ void add_h4(const float4* __restrict__ a, const float4* __restrict__ b,
                       __half2* __restrict__ out, int n4) {
    int i = blockIdx.x * blockDim.x + threadIdx.x;
    if (i < n4) {
        float4 x = a[i], y = b[i];
        out[2 * i]     = __floats2half2_rn(x.x + y.x, x.y + y.y);
        out[2 * i + 1] = __floats2half2_rn(x.z + y.z, x.w + y.w);
    }
}

// ---------------- bias concat ----------------
__global__ void concat_bias(const float* __restrict__ b_off, const float* __restrict__ b_att,
                            float* __restrict__ out) {
    int i = threadIdx.x + blockIdx.x * blockDim.x;
    if (i < 256) out[i] = b_off[i];
    else if (i < 384) out[i] = b_att[i - 256];
}

// ---------------- fp16 tensor-core GEMM, cp.async 3-stage ----------------
// C[M,N] = A[M,K](fp16) @ Bt[N,K](fp16, row=n) + bias (+ReLU).
// BM=128, BN=64, BK=32, 256 threads (8 warps, 4x2), warp tile 32x32,
// m16n8k16, fp32 accum. smem rows padded to 40 halves (80B) -> conflict-free.
#define AROW_W 20                          // uint32 words per smem row
#define A_WORDS (128 * AROW_W)             // 2560
#define B_WORDS (64 * AROW_W)              // 1280
#define SMEM_BYTES (3 * (A_WORDS + B_WORDS) * 4)   // 46080

template<bool RELU, bool HALF_OUT>
__global__ void __launch_bounds__(256) gemm_f16(
        const __half* __restrict__ A, const __half* __restrict__ Bt,
        const float* __restrict__ bias, void* __restrict__ Cv,
        int M, int N, int K) {
    extern __shared__ uint32_t smem[];
    uint32_t* As = smem;
    uint32_t* Bs = smem + 3 * A_WORDS;
    const uint32_t sAs = (uint32_t)__cvta_generic_to_shared(As);
    const uint32_t sBs = (uint32_t)__cvta_generic_to_shared(Bs);

    const int tid  = threadIdx.x;
    const int lane = tid & 31;
    const int warp = tid >> 5;
    const int wm   = warp & 3;
    const int wn   = warp >> 2;
    const int row0 = blockIdx.y * 128;
    const int col0 = blockIdx.x * 64;

    const int ntiles = K / 32;

    auto issue = [&](int kt, int st) {
        const int kg = kt * 32;
        const uint32_t aB = sAs + st * (A_WORDS * 4);
        const uint32_t bB = sBs + st * (B_WORDS * 4);
        const int chunk = tid & 3;          // 16B chunk (8 halves)
        #pragma unroll
        for (int i = 0; i < 2; i++) {
            int m = (tid >> 2) + i * 64;
            int gr = row0 + m;
            bool ok = gr < M;
            const __half* g = A + (size_t)(ok ? gr : 0) * K + kg + chunk * 8;
            cp16(aB + m * 80 + chunk * 16, g, ok);
        }
        {
            int n = tid >> 2;
            const __half* g = Bt + (size_t)(col0 + n) * K + kg + chunk * 8;
            cp16(bB + n * 80 + chunk * 16, g, true);
        }
        cp_commit();
    };

    float acc[2][4][4];
    #pragma unroll
    for (int t = 0; t < 2; t++)
        #pragma unroll
        for (int n = 0; n < 4; n++)
            #pragma unroll
            for (int j = 0; j < 4; j++) acc[t][n][j] = 0.f;

    issue(0, 0);
    if (ntiles > 1) issue(1, 1);

    const int q = lane & 3;
    const int r = lane >> 2;

    for (int kt = 0; kt < ntiles; kt++) {
        if (kt + 1 < ntiles) { asm volatile("cp.async.wait_group 1;\n"); }
        else                 { asm volatile("cp.async.wait_group 0;\n"); }
        __syncthreads();
        if (kt + 2 < ntiles) issue(kt + 2, (kt + 2) % 3);

        const int st = kt % 3;
        const uint32_t* Asb = As + st * A_WORDS;
        const uint32_t* Bsb = Bs + st * B_WORDS;

        #pragma unroll
        for (int ks = 0; ks < 2; ks++) {
            uint32_t af[2][4];
            #pragma unroll
            for (int t = 0; t < 2; t++) {
                int m = wm * 32 + t * 16 + r;
                int base = m * AROW_W + ks * 8 + q;
                af[t][0] = Asb[base];
                af[t][1] = Asb[base + 8 * AROW_W];
                af[t][2] = Asb[base + 4];
                af[t][3] = Asb[base + 8 * AROW_W + 4];
            }
            uint32_t bf[4][2];
            #pragma unroll
            for (int n = 0; n < 4; n++) {
                int nn = wn * 32 + n * 8 + r;
                int base = nn * AROW_W + ks * 8 + q;
                bf[n][0] = Bsb[base];
                bf[n][1] = Bsb[base + 4];
            }
            #pragma unroll
            for (int t = 0; t < 2; t++)
                #pragma unroll
                for (int n = 0; n < 4; n++)
                    mma_f16(acc[t][n][0], acc[t][n][1], acc[t][n][2], acc[t][n][3],
                            af[t][0], af[t][1], af[t][2], af[t][3],
                            bf[n][0], bf[n][1]);
        }
    }

    // ---- epilogue ----
    #pragma unroll
    for (int t = 0; t < 2; t++) {
        #pragma unroll
        for (int n = 0; n < 4; n++) {
            int gr = row0 + wm * 32 + t * 16 + r;
            int gc = col0 + wn * 32 + n * 8 + 2 * q;
            float b0 = bias[gc], b1 = bias[gc + 1];
            #pragma unroll
            for (int half_ = 0; half_ < 2; half_++) {
                int grr = gr + 8 * half_;
                if (grr >= M) continue;
                float v0 = acc[t][n][2 * half_]     + b0;
                float v1 = acc[t][n][2 * half_ + 1] + b1;
                if (RELU) { v0 = fmaxf(v0, 0.f); v1 = fmaxf(v1, 0.f); }
                if (HALF_OUT) {
                    __half2* C = (__half2*)Cv;
                    C[((size_t)grr * N + gc) >> 1] = __floats2half2_rn(v0, v1);
                } else {
                    float* C = (float*)Cv;
                    C[(size_t)grr * N + gc]     = v0;
                    C[(size_t)grr * N + gc + 1] = v1;
                }
            }
        }
    }
}

// ---------------- softmax over 16 attn weights, fused-oa layout ----------------
__global__ void softmax16s(float* __restrict__ oa, int n) {
    int i = blockIdx.x * blockDim.x + threadIdx.x;
    if (i >= n) return;
    float4* p = (float4*)(oa + (size_t)(i >> 3) * 384 + 256 + (i & 7) * 16);
    float v[16];
    float4 rr;
    #pragma unroll
    for (int j = 0; j < 4; j++) {
        rr = p[j];
        v[4*j] = rr.x; v[4*j+1] = rr.y; v[4*j+2] = rr.z; v[4*j+3] = rr.w;
    }
    float m = -1e30f;
    #pragma unroll
    for (int j = 0; j < 16; j++) m = fmaxf(m, v[j]);
    float s = 0.f;
    #pragma unroll
    for (int j = 0; j < 16; j++) { v[j] = __expf(v[j] - m); s += v[j]; }
    float inv = 1.f / s;
    #pragma unroll
    for (int j = 0; j < 16; j++) v[j] *= inv;
    #pragma unroll
    for (int j = 0; j < 4; j++)
        p[j] = make_float4(v[4*j], v[4*j+1], v[4*j+2], v[4*j+3]);
}

// ---------------- multi-scale deformable sampling (fp16 output) ----------------
__global__ void ms_sample(const float* __restrict__ val, const float* __restrict__ oa,
                          const float* __restrict__ ref, __half* __restrict__ out) {
    int token = blockIdx.x;
    int b = token / S_TOTAL;
    int h = threadIdx.x >> 5;
    int c = threadIdx.x & 31;

    const float* refp  = ref + (size_t)token * (N_LEVELS * 2);
    const float* offp  = oa  + (size_t)token * 384 + h * 32;
    const float* attnp = oa  + (size_t)token * 384 + 256 + h * 16;
    const float* vbase = val + (size_t)b * S_TOTAL * D_MODEL + h * D_HEAD + c;

    float acc = 0.f;
    #pragma unroll
    for (int l = 0; l < N_LEVELS; l++) {
        const int Hl = c_H[l], Wl = c_W[l];
        const float fH = (float)Hl, fW = (float)Wl;
        const float rx = refp[l * 2 + 0];
        const float ry = refp[l * 2 + 1];
        const float* vlev = vbase + (size_t)c_start[l] * D_MODEL;
        #pragma unroll
        for (int p = 0; p < N_POINTS; p++) {
            float ox = offp[l * 8 + p * 2 + 0];
            float oy = offp[l * 8 + p * 2 + 1];
            float px = (rx + ox / fW) * fW - 0.5f;
            float py = (ry + oy / fH) * fH - 0.5f;
            float x0 = floorf(px), y0 = floorf(py);
            float wx = px - x0, wy = py - y0;
            int x0i = (int)x0, y0i = (int)y0;
            float a = attnp[l * 4 + p];

            float s = 0.f;
            {
                int xi = x0i, yi = y0i;
                if (xi >= 0 && xi < Wl && yi >= 0 && yi < Hl)
                    s += (1.f - wx) * (1.f - wy) * vlev[(size_t)(yi * Wl + xi) * D_MODEL];
            }
            {
                int xi = x0i + 1, yi = y0i;
                if (xi >= 0 && xi < Wl && yi >= 0 && yi < Hl)
                    s += wx * (1.f - wy) * vlev[(size_t)(yi * Wl + xi) * D_MODEL];
            }
            {
                int xi = x0i, yi = y0i + 1;
                if (xi >= 0 && xi < Wl && yi >= 0 && yi < Hl)
                    s += (1.f - wx) * wy * vlev[(size_t)(yi * Wl + xi) * D_MODEL];
            }
            {
                int xi = x0i + 1, yi = y0i + 1;
                if (xi >= 0 && xi < Wl && yi >= 0 && yi < Hl)
                    s += wx * wy * vlev[(size_t)(yi * Wl + xi) * D_MODEL];
            }
            acc += a * s;
        }
    }
    out[(size_t)token * D_MODEL + h * D_HEAD + c] = __float2half(acc);
}

// ---------------- residual add + LayerNorm (optional fp16 aux output) ----------------
template<bool HALF_AUX>
__global__ void add_layernorm(const float* __restrict__ a, const float* __restrict__ b,
                              const float* __restrict__ gamma, const float* __restrict__ beta,
                              float* __restrict__ out, __half* __restrict__ outh) {
    __shared__ float red[8];
    int token = blockIdx.x;
    int c = threadIdx.x;
    float v = a[(size_t)token * D_MODEL + c] + b[(size_t)token * D_MODEL + c];

    float s = v;
    #pragma unroll
    for (int o = 16; o > 0; o >>= 1) s += __shfl_xor_sync(0xffffffffu, s, o);
    if ((c & 31) == 0) red[c >> 5] = s;
    __syncthreads();
    if (c < 8) {
        float t = red[c];
        #pragma unroll
        for (int o = 4; o > 0; o >>= 1) t += __shfl_xor_sync(0xffu, t, o);
        if (c == 0) red[0] = t;
    }
    __syncthreads();
    float mu = red[0] * (1.f / D_MODEL);
    __syncthreads();

    float d = v - mu;
    float ss = d * d;
    #pragma unroll
    for (int o = 16; o > 0; o >>= 1) ss += __shfl_xor_sync(0xffffffffu, ss, o);
    if ((c & 31) == 0) red[c >> 5] = ss;
    __syncthreads();
    if (c < 8) {
        float t = red[c];
        #pragma unroll
        for (int o = 4; o > 0; o >>= 1) t += __shfl_xor_sync(0xffu, t, o);
        if (c == 0) red[0] = t;
    }
    __syncthreads();
    float var = red[0] * (1.f / D_MODEL);
    float inv = rsqrtf(var + 1e-5f);

    float o_ = d * inv * gamma[c] + beta[c];
    out[(size_t)token * D_MODEL + c] = o_;
    if (HALF_AUX) outh[(size_t)token * D_MODEL + c] = __float2half(o_);
}

// ---------------- launch ----------------
extern "C" void kernel_launch(void* const* d_in, const int* in_sizes, int n_in,
                              void* d_out, int out_size) {
    const float* src   = (const float*)d_in[0];
    const float* pos   = (const float*)d_in[1];
    const float* ref   = (const float*)d_in[2];
    const float* W_off = (const float*)d_in[5];
    const float* b_off = (const float*)d_in[6];
    const float* W_att = (const float*)d_in[7];
    const float* b_att = (const float*)d_in[8];
    const float* W_val = (const float*)d_in[9];
    const float* b_val = (const float*)d_in[10];
    const float* W_out = (const float*)d_in[11];
    const float* b_out = (const float*)d_in[12];
    const float* ln1g  = (const float*)d_in[13];
    const float* ln1b  = (const float*)d_in[14];
    const float* W1    = (const float*)d_in[15];
    const float* b1    = (const float*)d_in[16];
    const float* W2    = (const float*)d_in[17];
    const float* b2    = (const float*)d_in[18];
    const float* ln2g  = (const float*)d_in[19];
    const float* ln2b  = (const float*)d_in[20];
    float* out = (float*)d_out;

    float  *val, *oa, *attno, *x, *ffn, *boa;
    __half *srch, *qh, *samph, *xh, *hh, *wt;
    cudaGetSymbolAddress((void**)&val,   g_val);
    cudaGetSymbolAddress((void**)&oa,    g_oa);
    cudaGetSymbolAddress((void**)&attno, g_attno);
    cudaGetSymbolAddress((void**)&x,     g_x);
    cudaGetSymbolAddress((void**)&ffn,   g_ffn);
    cudaGetSymbolAddress((void**)&srch,  g_srch);
    cudaGetSymbolAddress((void**)&qh,    g_qh);
    cudaGetSymbolAddress((void**)&samph, g_samph);
    cudaGetSymbolAddress((void**)&xh,    g_xh);
    cudaGetSymbolAddress((void**)&hh,    g_hh);
    cudaGetSymbolAddress((void**)&wt,    g_wt);
    cudaGetSymbolAddress((void**)&boa,   g_boa);

    const int M = TOKENS;
    const int MB = (M + 127) / 128;
    dim3 thr(256);

    // weights -> fp16 [N][K] transposed
    convT<<<dim3(256 / 32, 256 / 32),  thr>>>(W_val, wt + WT_VAL, 256, 256, 0);
    convT<<<dim3(256 / 32, 256 / 32),  thr>>>(W_off, wt + WT_OA,  256, 256, 0);
    convT<<<dim3(128 / 32, 256 / 32),  thr>>>(W_att, wt + WT_OA,  256, 128, 256);
    convT<<<dim3(256 / 32, 256 / 32),  thr>>>(W_out, wt + WT_OUT, 256, 256, 0);
    convT<<<dim3(1024 / 32, 256 / 32), thr>>>(W1,    wt + WT_W1,  256, 1024, 0);
    convT<<<dim3(256 / 32, 1024 / 32), thr>>>(W2,    wt + WT_W2,  1024, 256, 0);
    concat_bias<<<2, 192>>>(b_off, b_att, boa);

    // src -> fp16 ; q = fp16(src + pos)
    conv_h4<<<(M * D_MODEL / 4 + 255) / 256, thr>>>((const float4*)src, (__half2*)srch, M * D_MODEL / 4);
    add_h4<<<(M * D_MODEL / 4 + 255) / 256, thr>>>(
        (const float4*)src, (const float4*)pos, (__half2*)qh, M * D_MODEL / 4);

    // GEMMs (fp16 tensor cores)
    gemm_f16<false, false><<<dim3(4, MB), thr, SMEM_BYTES>>>(
        srch, wt + WT_VAL, b_val, val, M, 256, 256);
    gemm_f16<false, false><<<dim3(6, MB), thr, SMEM_BYTES>>>(
        qh, wt + WT_OA, boa, oa, M, 384, 256);

    softmax16s<<<(M * N_HEADS + 255) / 256, thr>>>(oa, M * N_HEADS);

    ms_sample<<<M, thr>>>(val, oa, ref, samph);

    gemm_f16<false, false><<<dim3(4, MB), thr, SMEM_BYTES>>>(
        samph, wt + WT_OUT, b_out, attno, M, 256, 256);

    add_layernorm<true><<<M, thr>>>(src, attno, ln1g, ln1b, x, xh);

    gemm_f16<true, true><<<dim3(16, MB), thr, SMEM_BYTES>>>(
        xh, wt + WT_W1, b1, hh, M, 1024, 256);
    gemm_f16<false, false><<<dim3(4, MB), thr, SMEM_BYTES>>>(
        hh, wt + WT_W2, b2, ffn, M, 256, 1024);

    add_layernorm<false><<<M, thr>>>(x, ffn, ln2g, ln2b, out, nullptr);
}

// round 8
// speedup vs baseline: 3.1443x; 1.2368x over previous
#include <cuda_runtime.h>
#include <cuda_fp16.h>
#include <cstdint>
#include <math.h>

// ---------------- static problem shape ----------------
#define BATCH     2
#define S_TOTAL   13294
#define TOKENS    (BATCH * S_TOTAL)     // 26588
#define D_MODEL   256
#define D_FC      1024
#define N_HEADS   8
#define N_LEVELS  4
#define N_POINTS  4
#define D_HEAD    32

__device__ __constant__ int c_H[4]     = {100, 50, 25, 13};
__device__ __constant__ int c_W[4]     = {100, 50, 25, 13};
__device__ __constant__ int c_start[4] = {0, 10000, 12500, 13125};

// ---------------- scratch (no cudaMalloc allowed) ----------------
__device__ float  g_oa     [TOKENS * 384];       // fused [off(256) | attn(128)]
__device__ float  g_attno  [TOKENS * D_MODEL];
__device__ float  g_x      [TOKENS * D_MODEL];
__device__ float  g_ffn    [TOKENS * D_MODEL];
__device__ __half g_valh   [TOKENS * D_MODEL];   // fp16 value projection
__device__ __half g_srch   [TOKENS * D_MODEL];   // fp16 src
__device__ __half g_qh     [TOKENS * D_MODEL];   // fp16 q = src+pos
__device__ __half g_samph  [TOKENS * D_MODEL];   // fp16 sampled
__device__ __half g_xh     [TOKENS * D_MODEL];   // fp16 LN1 out
__device__ __half g_hh     [TOKENS * D_FC];      // fp16 ffn hidden
__device__ __half g_wt     [753664];             // fp16 transposed weights [N][K]
__device__ float  g_boa    [384];                // concat bias off|attn

// offsets in g_wt (halves)
#define WT_VAL 0
#define WT_OA  65536          // 384 x 256
#define WT_OUT 163840         // 256 x 256
#define WT_W1  229376         // 1024 x 256
#define WT_W2  491520         // 256 x 1024

// ---------------- mma fp16 helper ----------------
__device__ __forceinline__ void mma_f16(float& d0, float& d1, float& d2, float& d3,
                                        uint32_t a0, uint32_t a1, uint32_t a2, uint32_t a3,
                                        uint32_t b0, uint32_t b1) {
    asm volatile(
        "mma.sync.aligned.m16n8k16.row.col.f32.f16.f16.f32 "
        "{%0,%1,%2,%3}, {%4,%5,%6,%7}, {%8,%9}, {%0,%1,%2,%3};\n"
        : "+f"(d0), "+f"(d1), "+f"(d2), "+f"(d3)
        : "r"(a0), "r"(a1), "r"(a2), "r"(a3), "r"(b0), "r"(b1));
}

// ---------------- cp.async helpers ----------------
__device__ __forceinline__ void cp16(uint32_t smem_addr, const void* gmem, bool pred) {
    int sz = pred ? 16 : 0;
    asm volatile("cp.async.cg.shared.global [%0], [%1], 16, %2;\n"
                 :: "r"(smem_addr), "l"(gmem), "r"(sz));
}
__device__ __forceinline__ void cp_commit() {
    asm volatile("cp.async.commit_group;\n");
}

// ---------------- weight transpose + fp16 convert ----------------
__global__ void convT(const float* __restrict__ in, __half* __restrict__ out,
                      int K, int N, int rowOff) {
    __shared__ float t[32][33];
    int k0 = blockIdx.y * 32, n0 = blockIdx.x * 32;
    int tx = threadIdx.x & 31, ty = threadIdx.x >> 5;
    #pragma unroll
    for (int i = 0; i < 32; i += 8)
        t[ty + i][tx] = in[(size_t)(k0 + ty + i) * N + n0 + tx];
    __syncthreads();
    #pragma unroll
    for (int i = 0; i < 32; i += 8)
        out[(size_t)(rowOff + n0 + ty + i) * K + k0 + tx] = __float2half(t[tx][ty + i]);
}

// ---------------- fused: srch = fp16(src); qh = fp16(src + pos) ----------------
__global__ void prep_h(const float4* __restrict__ src, const float4* __restrict__ pos,
                       __half2* __restrict__ srch, __half2* __restrict__ qh, int n4) {
    int i = blockIdx.x * blockDim.x + threadIdx.x;
    if (i < n4) {
        float4 s = src[i], p = pos[i];
        srch[2 * i]     = __floats2half2_rn(s.x, s.y);
        srch[2 * i + 1] = __floats2half2_rn(s.z, s.w);
        qh[2 * i]       = __floats2half2_rn(s.x + p.x, s.y + p.y);
        qh[2 * i + 1]   = __floats2half2_rn(s.z + p.z, s.w + p.w);
    }
}

// ---------------- bias concat ----------------
__global__ void concat_bias(const float* __restrict__ b_off, const float* __restrict__ b_att,
                            float* __restrict__ out) {
    int i = threadIdx.x + blockIdx.x * blockDim.x;
    if (i < 256) out[i] = b_off[i];
    else if (i < 384) out[i] = b_att[i - 256];
}

// ---------------- fp16 tensor-core GEMM, cp.async 3-stage ----------------
#define AROW_W 20
#define A_WORDS (128 * AROW_W)
#define B_WORDS (64 * AROW_W)
#define SMEM_BYTES (3 * (A_WORDS + B_WORDS) * 4)   // 46080

template<bool RELU, bool HALF_OUT>
__global__ void __launch_bounds__(256) gemm_f16(
        const __half* __restrict__ A, const __half* __restrict__ Bt,
        const float* __restrict__ bias, void* __restrict__ Cv,
        int M, int N, int K) {
    extern __shared__ uint32_t smem[];
    uint32_t* As = smem;
    uint32_t* Bs = smem + 3 * A_WORDS;
    const uint32_t sAs = (uint32_t)__cvta_generic_to_shared(As);
    const uint32_t sBs = (uint32_t)__cvta_generic_to_shared(Bs);

    const int tid  = threadIdx.x;
    const int lane = tid & 31;
    const int warp = tid >> 5;
    const int wm   = warp & 3;
    const int wn   = warp >> 2;
    const int row0 = blockIdx.y * 128;
    const int col0 = blockIdx.x * 64;

    const int ntiles = K / 32;

    auto issue = [&](int kt, int st) {
        const int kg = kt * 32;
        const uint32_t aB = sAs + st * (A_WORDS * 4);
        const uint32_t bB = sBs + st * (B_WORDS * 4);
        const int chunk = tid & 3;
        #pragma unroll
        for (int i = 0; i < 2; i++) {
            int m = (tid >> 2) + i * 64;
            int gr = row0 + m;
            bool ok = gr < M;
            const __half* g = A + (size_t)(ok ? gr : 0) * K + kg + chunk * 8;
            cp16(aB + m * 80 + chunk * 16, g, ok);
        }
        {
            int n = tid >> 2;
            const __half* g = Bt + (size_t)(col0 + n) * K + kg + chunk * 8;
            cp16(bB + n * 80 + chunk * 16, g, true);
        }
        cp_commit();
    };

    float acc[2][4][4];
    #pragma unroll
    for (int t = 0; t < 2; t++)
        #pragma unroll
        for (int n = 0; n < 4; n++)
            #pragma unroll
            for (int j = 0; j < 4; j++) acc[t][n][j] = 0.f;

    issue(0, 0);
    if (ntiles > 1) issue(1, 1);

    const int q = lane & 3;
    const int r = lane >> 2;

    for (int kt = 0; kt < ntiles; kt++) {
        if (kt + 1 < ntiles) { asm volatile("cp.async.wait_group 1;\n"); }
        else                 { asm volatile("cp.async.wait_group 0;\n"); }
        __syncthreads();
        if (kt + 2 < ntiles) issue(kt + 2, (kt + 2) % 3);

        const int st = kt % 3;
        const uint32_t* Asb = As + st * A_WORDS;
        const uint32_t* Bsb = Bs + st * B_WORDS;

        #pragma unroll
        for (int ks = 0; ks < 2; ks++) {
            uint32_t af[2][4];
            #pragma unroll
            for (int t = 0; t < 2; t++) {
                int m = wm * 32 + t * 16 + r;
                int base = m * AROW_W + ks * 8 + q;
                af[t][0] = Asb[base];
                af[t][1] = Asb[base + 8 * AROW_W];
                af[t][2] = Asb[base + 4];
                af[t][3] = Asb[base + 8 * AROW_W + 4];
            }
            uint32_t bf[4][2];
            #pragma unroll
            for (int n = 0; n < 4; n++) {
                int nn = wn * 32 + n * 8 + r;
                int base = nn * AROW_W + ks * 8 + q;
                bf[n][0] = Bsb[base];
                bf[n][1] = Bsb[base + 4];
            }
            #pragma unroll
            for (int t = 0; t < 2; t++)
                #pragma unroll
                for (int n = 0; n < 4; n++)
                    mma_f16(acc[t][n][0], acc[t][n][1], acc[t][n][2], acc[t][n][3],
                            af[t][0], af[t][1], af[t][2], af[t][3],
                            bf[n][0], bf[n][1]);
        }
    }

    // ---- epilogue ----
    #pragma unroll
    for (int t = 0; t < 2; t++) {
        #pragma unroll
        for (int n = 0; n < 4; n++) {
            int gr = row0 + wm * 32 + t * 16 + r;
            int gc = col0 + wn * 32 + n * 8 + 2 * q;
            float b0 = bias[gc], b1 = bias[gc + 1];
            #pragma unroll
            for (int half_ = 0; half_ < 2; half_++) {
                int grr = gr + 8 * half_;
                if (grr >= M) continue;
                float v0 = acc[t][n][2 * half_]     + b0;
                float v1 = acc[t][n][2 * half_ + 1] + b1;
                if (RELU) { v0 = fmaxf(v0, 0.f); v1 = fmaxf(v1, 0.f); }
                if (HALF_OUT) {
                    __half2* C = (__half2*)Cv;
                    C[((size_t)grr * N + gc) >> 1] = __floats2half2_rn(v0, v1);
                } else {
                    float* C = (float*)Cv;
                    C[(size_t)grr * N + gc]     = v0;
                    C[(size_t)grr * N + gc + 1] = v1;
                }
            }
        }
    }
}

// ---------------- softmax over 16 attn weights, fused-oa layout ----------------
__global__ void softmax16s(float* __restrict__ oa, int n) {
    int i = blockIdx.x * blockDim.x + threadIdx.x;
    if (i >= n) return;
    float4* p = (float4*)(oa + (size_t)(i >> 3) * 384 + 256 + (i & 7) * 16);
    float v[16];
    float4 rr;
    #pragma unroll
    for (int j = 0; j < 4; j++) {
        rr = p[j];
        v[4*j] = rr.x; v[4*j+1] = rr.y; v[4*j+2] = rr.z; v[4*j+3] = rr.w;
    }
    float m = -1e30f;
    #pragma unroll
    for (int j = 0; j < 16; j++) m = fmaxf(m, v[j]);
    float s = 0.f;
    #pragma unroll
    for (int j = 0; j < 16; j++) { v[j] = __expf(v[j] - m); s += v[j]; }
    float inv = 1.f / s;
    #pragma unroll
    for (int j = 0; j < 16; j++) v[j] *= inv;
    #pragma unroll
    for (int j = 0; j < 4; j++)
        p[j] = make_float4(v[4*j], v[4*j+1], v[4*j+2], v[4*j+3]);
}

// ---------------- multi-scale deformable sampling, fp16 values, half2 lanes ----------
// block = 256 thr = 8 warps = 2 tokens; warp covers 2 heads (16 lanes each);
// lane-within-group = channel pair (half2).
__global__ void ms_sample_h(const __half2* __restrict__ valh, const float* __restrict__ oa,
                            const float* __restrict__ ref, __half2* __restrict__ out) {
    const int warp = threadIdx.x >> 5;
    const int lane = threadIdx.x & 31;
    const int token = blockIdx.x * 2 + (warp >> 2);
    const int h  = ((warp & 3) << 1) + (lane >> 4);   // head 0..7
    const int cp = lane & 15;                         // channel pair 0..15
    const int b = token / S_TOTAL;

    const float* refp  = ref + (size_t)token * (N_LEVELS * 2);
    const float* offp  = oa  + (size_t)token * 384 + h * 32;
    const float* attnp = oa  + (size_t)token * 384 + 256 + h * 16;
    const __half2* vbase = valh + (size_t)b * S_TOTAL * 128 + h * 16 + cp;

    float2 acc = make_float2(0.f, 0.f);
    #pragma unroll
    for (int l = 0; l < N_LEVELS; l++) {
        const int Hl = c_H[l], Wl = c_W[l];
        const float fH = (float)Hl, fW = (float)Wl;
        const float rx = refp[l * 2 + 0];
        const float ry = refp[l * 2 + 1];
        const __half2* vlev = vbase + (size_t)c_start[l] * 128;
        #pragma unroll
        for (int p = 0; p < N_POINTS; p++) {
            float ox = offp[l * 8 + p * 2 + 0];
            float oy = offp[l * 8 + p * 2 + 1];
            float px = (rx + ox / fW) * fW - 0.5f;
            float py = (ry + oy / fH) * fH - 0.5f;
            float x0 = floorf(px), y0 = floorf(py);
            float wx = px - x0, wy = py - y0;
            int x0i = (int)x0, y0i = (int)y0;
            float a = attnp[l * 4 + p];

            float2 s = make_float2(0.f, 0.f);
            {
                if (x0i >= 0 && x0i < Wl && y0i >= 0 && y0i < Hl) {
                    float w = (1.f - wx) * (1.f - wy);
                    float2 v = __half22float2(vlev[(size_t)(y0i * Wl + x0i) * 128]);
                    s.x += w * v.x; s.y += w * v.y;
                }
            }
            {
                int xi = x0i + 1;
                if (xi >= 0 && xi < Wl && y0i >= 0 && y0i < Hl) {
                    float w = wx * (1.f - wy);
                    float2 v = __half22float2(vlev[(size_t)(y0i * Wl + xi) * 128]);
                    s.x += w * v.x; s.y += w * v.y;
                }
            }
            {
                int yi = y0i + 1;
                if (x0i >= 0 && x0i < Wl && yi >= 0 && yi < Hl) {
                    float w = (1.f - wx) * wy;
                    float2 v = __half22float2(vlev[(size_t)(yi * Wl + x0i) * 128]);
                    s.x += w * v.x; s.y += w * v.y;
                }
            }
            {
                int xi = x0i + 1, yi = y0i + 1;
                if (xi >= 0 && xi < Wl && yi >= 0 && yi < Hl) {
                    float w = wx * wy;
                    float2 v = __half22float2(vlev[(size_t)(yi * Wl + xi) * 128]);
                    s.x += w * v.x; s.y += w * v.y;
                }
            }
            acc.x += a * s.x;
            acc.y += a * s.y;
        }
    }
    out[(size_t)token * 128 + h * 16 + cp] = __floats2half2_rn(acc.x, acc.y);
}

// ---------------- residual add + LayerNorm (optional fp16 aux output) ----------------
template<bool HALF_AUX>
__global__ void add_layernorm(const float* __restrict__ a, const float* __restrict__ b,
                              const float* __restrict__ gamma, const float* __restrict__ beta,
                              float* __restrict__ out, __half* __restrict__ outh) {
    __shared__ float red[8];
    int token = blockIdx.x;
    int c = threadIdx.x;
    float v = a[(size_t)token * D_MODEL + c] + b[(size_t)token * D_MODEL + c];

    float s = v;
    #pragma unroll
    for (int o = 16; o > 0; o >>= 1) s += __shfl_xor_sync(0xffffffffu, s, o);
    if ((c & 31) == 0) red[c >> 5] = s;
    __syncthreads();
    if (c < 8) {
        float t = red[c];
        #pragma unroll
        for (int o = 4; o > 0; o >>= 1) t += __shfl_xor_sync(0xffu, t, o);
        if (c == 0) red[0] = t;
    }
    __syncthreads();
    float mu = red[0] * (1.f / D_MODEL);
    __syncthreads();

    float d = v - mu;
    float ss = d * d;
    #pragma unroll
    for (int o = 16; o > 0; o >>= 1) ss += __shfl_xor_sync(0xffffffffu, ss, o);
    if ((c & 31) == 0) red[c >> 5] = ss;
    __syncthreads();
    if (c < 8) {
        float t = red[c];
        #pragma unroll
        for (int o = 4; o > 0; o >>= 1) t += __shfl_xor_sync(0xffu, t, o);
        if (c == 0) red[0] = t;
    }
    __syncthreads();
    float var = red[0] * (1.f / D_MODEL);
    float inv = rsqrtf(var + 1e-5f);

    float o_ = d * inv * gamma[c] + beta[c];
    out[(size_t)token * D_MODEL + c] = o_;
    if (HALF_AUX) outh[(size_t)token * D_MODEL + c] = __float2half(o_);
}

// ---------------- launch ----------------
extern "C" void kernel_launch(void* const* d_in, const int* in_sizes, int n_in,
                              void* d_out, int out_size) {
    const float* src   = (const float*)d_in[0];
    const float* pos   = (const float*)d_in[1];
    const float* ref   = (const float*)d_in[2];
    const float* W_off = (const float*)d_in[5];
    const float* b_off = (const float*)d_in[6];
    const float* W_att = (const float*)d_in[7];
    const float* b_att = (const float*)d_in[8];
    const float* W_val = (const float*)d_in[9];
    const float* b_val = (const float*)d_in[10];
    const float* W_out = (const float*)d_in[11];
    const float* b_out = (const float*)d_in[12];
    const float* ln1g  = (const float*)d_in[13];
    const float* ln1b  = (const float*)d_in[14];
    const float* W1    = (const float*)d_in[15];
    const float* b1    = (const float*)d_in[16];
    const float* W2    = (const float*)d_in[17];
    const float* b2    = (const float*)d_in[18];
    const float* ln2g  = (const float*)d_in[19];
    const float* ln2b  = (const float*)d_in[20];
    float* out = (float*)d_out;

    float  *oa, *attno, *x, *ffn, *boa;
    __half *valh, *srch, *qh, *samph, *xh, *hh, *wt;
    cudaGetSymbolAddress((void**)&oa,    g_oa);
    cudaGetSymbolAddress((void**)&attno, g_attno);
    cudaGetSymbolAddress((void**)&x,     g_x);
    cudaGetSymbolAddress((void**)&ffn,   g_ffn);
    cudaGetSymbolAddress((void**)&valh,  g_valh);
    cudaGetSymbolAddress((void**)&srch,  g_srch);
    cudaGetSymbolAddress((void**)&qh,    g_qh);
    cudaGetSymbolAddress((void**)&samph, g_samph);
    cudaGetSymbolAddress((void**)&xh,    g_xh);
    cudaGetSymbolAddress((void**)&hh,    g_hh);
    cudaGetSymbolAddress((void**)&wt,    g_wt);
    cudaGetSymbolAddress((void**)&boa,   g_boa);

    const int M = TOKENS;
    const int MB = (M + 127) / 128;
    dim3 thr(256);

    // weights -> fp16 [N][K] transposed
    convT<<<dim3(256 / 32, 256 / 32),  thr>>>(W_val, wt + WT_VAL, 256, 256, 0);
    convT<<<dim3(256 / 32, 256 / 32),  thr>>>(W_off, wt + WT_OA,  256, 256, 0);
    convT<<<dim3(128 / 32, 256 / 32),  thr>>>(W_att, wt + WT_OA,  256, 128, 256);
    convT<<<dim3(256 / 32, 256 / 32),  thr>>>(W_out, wt + WT_OUT, 256, 256, 0);
    convT<<<dim3(1024 / 32, 256 / 32), thr>>>(W1,    wt + WT_W1,  256, 1024, 0);
    convT<<<dim3(256 / 32, 1024 / 32), thr>>>(W2,    wt + WT_W2,  1024, 256, 0);
    concat_bias<<<2, 192>>>(b_off, b_att, boa);

    // srch = fp16(src); qh = fp16(src + pos)
    prep_h<<<(M * D_MODEL / 4 + 255) / 256, thr>>>(
        (const float4*)src, (const float4*)pos, (__half2*)srch, (__half2*)qh, M * D_MODEL / 4);

    // GEMMs (fp16 tensor cores)
    gemm_f16<false, true><<<dim3(4, MB), thr, SMEM_BYTES>>>(
        srch, wt + WT_VAL, b_val, valh, M, 256, 256);
    gemm_f16<false, false><<<dim3(6, MB), thr, SMEM_BYTES>>>(
        qh, wt + WT_OA, boa, oa, M, 384, 256);

    softmax16s<<<(M * N_HEADS + 255) / 256, thr>>>(oa, M * N_HEADS);

    ms_sample_h<<<M / 2, thr>>>((const __half2*)valh, oa, ref, (__half2*)samph);

    gemm_f16<false, false><<<dim3(4, MB), thr, SMEM_BYTES>>>(
        samph, wt + WT_OUT, b_out, attno, M, 256, 256);

    add_layernorm<true><<<M, thr>>>(src, attno, ln1g, ln1b, x, xh);

    gemm_f16<true, true><<<dim3(16, MB), thr, SMEM_BYTES>>>(
        xh, wt + WT_W1, b1, hh, M, 1024, 256);
    gemm_f16<false, false><<<dim3(4, MB), thr, SMEM_BYTES>>>(
        hh, wt + WT_W2, b2, ffn, M, 256, 1024);

    add_layernorm<false><<<M, thr>>>(x, ffn, ln2g, ln2b, out, nullptr);
}

// round 10
// speedup vs baseline: 3.2820x; 1.0438x over previous
#include <cuda_runtime.h>
#include <cuda_fp16.h>
#include <cstdint>
#include <math.h>

// ---------------- static problem shape ----------------
#define BATCH     2
#define S_TOTAL   13294
#define TOKENS    (BATCH * S_TOTAL)     // 26588
#define D_MODEL   256
#define D_FC      1024
#define N_HEADS   8
#define N_LEVELS  4
#define N_POINTS  4
#define D_HEAD    32

__device__ __constant__ int c_H[4]     = {100, 50, 25, 13};
__device__ __constant__ int c_W[4]     = {100, 50, 25, 13};
__device__ __constant__ int c_start[4] = {0, 10000, 12500, 13125};

// ---------------- scratch (no cudaMalloc allowed) ----------------
__device__ float  g_oa     [TOKENS * 384];       // fused [off(256) | attn_logits(128)]
__device__ float  g_attno  [TOKENS * D_MODEL];
__device__ float  g_x      [TOKENS * D_MODEL];
__device__ float  g_ffn    [TOKENS * D_MODEL];
__device__ __half g_valh   [TOKENS * D_MODEL];   // fp16 value projection
__device__ __half g_srch   [TOKENS * D_MODEL];   // fp16 src
__device__ __half g_qh     [TOKENS * D_MODEL];   // fp16 q = src+pos
__device__ __half g_samph  [TOKENS * D_MODEL];   // fp16 sampled
__device__ __half g_xh     [TOKENS * D_MODEL];   // fp16 LN1 out
__device__ __half g_hh     [TOKENS * D_FC];      // fp16 ffn hidden
__device__ __half g_wt     [753664];             // fp16 transposed weights [N][K]
__device__ float  g_boa    [384];                // concat bias off|attn

// offsets in g_wt (halves)
#define WT_VAL 0
#define WT_OA  65536          // 384 x 256
#define WT_OUT 163840         // 256 x 256
#define WT_W1  229376         // 1024 x 256
#define WT_W2  491520         // 256 x 1024

// ---------------- mma fp16 helper ----------------
__device__ __forceinline__ void mma_f16(float& d0, float& d1, float& d2, float& d3,
                                        uint32_t a0, uint32_t a1, uint32_t a2, uint32_t a3,
                                        uint32_t b0, uint32_t b1) {
    asm volatile(
        "mma.sync.aligned.m16n8k16.row.col.f32.f16.f16.f32 "
        "{%0,%1,%2,%3}, {%4,%5,%6,%7}, {%8,%9}, {%0,%1,%2,%3};\n"
        : "+f"(d0), "+f"(d1), "+f"(d2), "+f"(d3)
        : "r"(a0), "r"(a1), "r"(a2), "r"(a3), "r"(b0), "r"(b1));
}

// ---------------- cp.async helpers ----------------
__device__ __forceinline__ void cp16(uint32_t smem_addr, const void* gmem, bool pred) {
    int sz = pred ? 16 : 0;
    asm volatile("cp.async.cg.shared.global [%0], [%1], 16, %2;\n"
                 :: "r"(smem_addr), "l"(gmem), "r"(sz));
}
__device__ __forceinline__ void cp_commit() {
    asm volatile("cp.async.commit_group;\n");
}

// ---------------- fused weight prep: 5 transposes + bias concat, one launch -------
// in: fp32 [K][N] row-major; out: fp16 [N][K] at (rowOff+n)*K + k
__global__ void __launch_bounds__(256) prep_weights(
        const float* __restrict__ Wv, const float* __restrict__ Wo,
        const float* __restrict__ Wa, const float* __restrict__ Wu,
        const float* __restrict__ W1, const float* __restrict__ W2,
        const float* __restrict__ b_off, const float* __restrict__ b_att,
        __half* __restrict__ wt, float* __restrict__ boa) {
    const int tid = threadIdx.x;
    const int bx  = blockIdx.x;
    if (bx == 0) {
        boa[tid] = b_off[tid];
        if (tid < 128) boa[256 + tid] = b_att[tid];
    }

    const float* in; __half* out;
    int K, N, rowOff, base, tilesX;
    if      (bx < 64)  { in = Wv; out = wt + WT_VAL; K = 256;  N = 256;  rowOff = 0;   base = 0;   tilesX = 8;  }
    else if (bx < 128) { in = Wo; out = wt + WT_OA;  K = 256;  N = 256;  rowOff = 0;   base = 64;  tilesX = 8;  }
    else if (bx < 160) { in = Wa; out = wt + WT_OA;  K = 256;  N = 128;  rowOff = 256; base = 128; tilesX = 4;  }
    else if (bx < 224) { in = Wu; out = wt + WT_OUT; K = 256;  N = 256;  rowOff = 0;   base = 160; tilesX = 8;  }
    else if (bx < 480) { in = W1; out = wt + WT_W1;  K = 256;  N = 1024; rowOff = 0;   base = 224; tilesX = 32; }
    else               { in = W2; out = wt + WT_W2;  K = 1024; N = 256;  rowOff = 0;   base = 480; tilesX = 8;  }

    const int local = bx - base;
    const int n0 = (local % tilesX) * 32;
    const int k0 = (local / tilesX) * 32;

    __shared__ float t[32][33];
    const int tx = tid & 31, ty = tid >> 5;
    #pragma unroll
    for (int i = 0; i < 32; i += 8)
        t[ty + i][tx] = in[(size_t)(k0 + ty + i) * N + n0 + tx];
    __syncthreads();
    #pragma unroll
    for (int i = 0; i < 32; i += 8)
        out[(size_t)(rowOff + n0 + ty + i) * K + k0 + tx] = __float2half(t[tx][ty + i]);
}

// ---------------- fused: srch = fp16(src); qh = fp16(src + pos) ----------------
__global__ void prep_h(const float4* __restrict__ src, const float4* __restrict__ pos,
                       __half2* __restrict__ srch, __half2* __restrict__ qh, int n4) {
    int i = blockIdx.x * blockDim.x + threadIdx.x;
    if (i < n4) {
        float4 s = src[i], p = pos[i];
        srch[2 * i]     = __floats2half2_rn(s.x, s.y);
        srch[2 * i + 1] = __floats2half2_rn(s.z, s.w);
        qh[2 * i]       = __floats2half2_rn(s.x + p.x, s.y + p.y);
        qh[2 * i + 1]   = __floats2half2_rn(s.z + p.z, s.w + p.w);
    }
}

// ---------------- fp16 tensor-core GEMM, cp.async 3-stage ----------------
#define AROW_W 20
#define A_WORDS (128 * AROW_W)
#define B_WORDS (64 * AROW_W)
#define SMEM_BYTES (3 * (A_WORDS + B_WORDS) * 4)   // 46080

template<bool RELU, bool HALF_OUT>
__global__ void __launch_bounds__(256) gemm_f16(
        const __half* __restrict__ A, const __half* __restrict__ Bt,
        const float* __restrict__ bias, void* __restrict__ Cv,
        int M, int N, int K) {
    extern __shared__ uint32_t smem[];
    uint32_t* As = smem;
    uint32_t* Bs = smem + 3 * A_WORDS;
    const uint32_t sAs = (uint32_t)__cvta_generic_to_shared(As);
    const uint32_t sBs = (uint32_t)__cvta_generic_to_shared(Bs);

    const int tid  = threadIdx.x;
    const int lane = tid & 31;
    const int warp = tid >> 5;
    const int wm   = warp & 3;
    const int wn   = warp >> 2;
    const int row0 = blockIdx.y * 128;
    const int col0 = blockIdx.x * 64;

    const int ntiles = K / 32;

    auto issue = [&](int kt, int st) {
        const int kg = kt * 32;
        const uint32_t aB = sAs + st * (A_WORDS * 4);
        const uint32_t bB = sBs + st * (B_WORDS * 4);
        const int chunk = tid & 3;
        #pragma unroll
        for (int i = 0; i < 2; i++) {
            int m = (tid >> 2) + i * 64;
            int gr = row0 + m;
            bool ok = gr < M;
            const __half* g = A + (size_t)(ok ? gr : 0) * K + kg + chunk * 8;
            cp16(aB + m * 80 + chunk * 16, g, ok);
        }
        {
            int n = tid >> 2;
            const __half* g = Bt + (size_t)(col0 + n) * K + kg + chunk * 8;
            cp16(bB + n * 80 + chunk * 16, g, true);
        }
        cp_commit();
    };

    float acc[2][4][4];
    #pragma unroll
    for (int t = 0; t < 2; t++)
        #pragma unroll
        for (int n = 0; n < 4; n++)
            #pragma unroll
            for (int j = 0; j < 4; j++) acc[t][n][j] = 0.f;

    issue(0, 0);
    if (ntiles > 1) issue(1, 1);

    const int q = lane & 3;
    const int r = lane >> 2;

    for (int kt = 0; kt < ntiles; kt++) {
        if (kt + 1 < ntiles) { asm volatile("cp.async.wait_group 1;\n"); }
        else                 { asm volatile("cp.async.wait_group 0;\n"); }
        __syncthreads();
        if (kt + 2 < ntiles) issue(kt + 2, (kt + 2) % 3);

        const int st = kt % 3;
        const uint32_t* Asb = As + st * A_WORDS;
        const uint32_t* Bsb = Bs + st * B_WORDS;

        #pragma unroll
        for (int ks = 0; ks < 2; ks++) {
            uint32_t af[2][4];
            #pragma unroll
            for (int t = 0; t < 2; t++) {
                int m = wm * 32 + t * 16 + r;
                int base = m * AROW_W + ks * 8 + q;
                af[t][0] = Asb[base];
                af[t][1] = Asb[base + 8 * AROW_W];
                af[t][2] = Asb[base + 4];
                af[t][3] = Asb[base + 8 * AROW_W + 4];
            }
            uint32_t bf[4][2];
            #pragma unroll
            for (int n = 0; n < 4; n++) {
                int nn = wn * 32 + n * 8 + r;
                int base = nn * AROW_W + ks * 8 + q;
                bf[n][0] = Bsb[base];
                bf[n][1] = Bsb[base + 4];
            }
            #pragma unroll
            for (int t = 0; t < 2; t++)
                #pragma unroll
                for (int n = 0; n < 4; n++)
                    mma_f16(acc[t][n][0], acc[t][n][1], acc[t][n][2], acc[t][n][3],
                            af[t][0], af[t][1], af[t][2], af[t][3],
                            bf[n][0], bf[n][1]);
        }
    }

    // ---- epilogue ----
    #pragma unroll
    for (int t = 0; t < 2; t++) {
        #pragma unroll
        for (int n = 0; n < 4; n++) {
            int gr = row0 + wm * 32 + t * 16 + r;
            int gc = col0 + wn * 32 + n * 8 + 2 * q;
            float b0 = bias[gc], b1 = bias[gc + 1];
            #pragma unroll
            for (int half_ = 0; half_ < 2; half_++) {
                int grr = gr + 8 * half_;
                if (grr >= M) continue;
                float v0 = acc[t][n][2 * half_]     + b0;
                float v1 = acc[t][n][2 * half_ + 1] + b1;
                if (RELU) { v0 = fmaxf(v0, 0.f); v1 = fmaxf(v1, 0.f); }
                if (HALF_OUT) {
                    __half2* C = (__half2*)Cv;
                    C[((size_t)grr * N + gc) >> 1] = __floats2half2_rn(v0, v1);
                } else {
                    float* C = (float*)Cv;
                    C[(size_t)grr * N + gc]     = v0;
                    C[(size_t)grr * N + gc + 1] = v1;
                }
            }
        }
    }
}

// ---------------- multi-scale deformable sampling, fused softmax -----------------
// block = 256 thr = 8 warps = 2 tokens; warp covers 2 heads (16 lanes each);
// lane-within-group = channel pair (half2). Softmax over the 16 attn logits is
// computed in-register across the 16-lane group (shfl), no separate pass.
__global__ void ms_sample_h(const __half2* __restrict__ valh, const float* __restrict__ oa,
                            const float* __restrict__ ref, __half2* __restrict__ out) {
    const int warp = threadIdx.x >> 5;
    const int lane = threadIdx.x & 31;
    const int token = blockIdx.x * 2 + (warp >> 2);
    const int h  = ((warp & 3) << 1) + (lane >> 4);   // head 0..7
    const int cp = lane & 15;                         // channel pair 0..15
    const int b = token / S_TOTAL;

    const float* refp  = ref + (size_t)token * (N_LEVELS * 2);
    const float* offp  = oa  + (size_t)token * 384 + h * 32;
    const float* attnp = oa  + (size_t)token * 384 + 256 + h * 16;
    const __half2* vbase = valh + (size_t)b * S_TOTAL * 128 + h * 16 + cp;

    // ---- in-register softmax over the 16-lane group ----
    float logit = attnp[cp];
    float m_ = logit;
    #pragma unroll
    for (int o = 8; o > 0; o >>= 1) m_ = fmaxf(m_, __shfl_xor_sync(0xffffffffu, m_, o));
    float e = __expf(logit - m_);
    float ssum = e;
    #pragma unroll
    for (int o = 8; o > 0; o >>= 1) ssum += __shfl_xor_sync(0xffffffffu, ssum, o);
    const float aval = e / ssum;
    const int grp = lane & 16;

    float2 acc = make_float2(0.f, 0.f);
    #pragma unroll
    for (int l = 0; l < N_LEVELS; l++) {
        const int Hl = c_H[l], Wl = c_W[l];
        const float fH = (float)Hl, fW = (float)Wl;
        const float rx = refp[l * 2 + 0];
        const float ry = refp[l * 2 + 1];
        const __half2* vlev = vbase + (size_t)c_start[l] * 128;
        #pragma unroll
        for (int p = 0; p < N_POINTS; p++) {
            float ox = offp[l * 8 + p * 2 + 0];
            float oy = offp[l * 8 + p * 2 + 1];
            float px = (rx + ox / fW) * fW - 0.5f;
            float py = (ry + oy / fH) * fH - 0.5f;
            float x0 = floorf(px), y0 = floorf(py);
            float wx = px - x0, wy = py - y0;
            int x0i = (int)x0, y0i = (int)y0;
            float a = __shfl_sync(0xffffffffu, aval, grp | (l * 4 + p));

            float2 s = make_float2(0.f, 0.f);
            {
                if (x0i >= 0 && x0i < Wl && y0i >= 0 && y0i < Hl) {
                    float w = (1.f - wx) * (1.f - wy);
                    float2 v = __half22float2(vlev[(size_t)(y0i * Wl + x0i) * 128]);
                    s.x += w * v.x; s.y += w * v.y;
                }
            }
            {
                int xi = x0i + 1;
                if (xi >= 0 && xi < Wl && y0i >= 0 && y0i < Hl) {
                    float w = wx * (1.f - wy);
                    float2 v = __half22float2(vlev[(size_t)(y0i * Wl + xi) * 128]);
                    s.x += w * v.x; s.y += w * v.y;
                }
            }
            {
                int yi = y0i + 1;
                if (x0i >= 0 && x0i < Wl && yi >= 0 && yi < Hl) {
                    float w = (1.f - wx) * wy;
                    float2 v = __half22float2(vlev[(size_t)(yi * Wl + x0i) * 128]);
                    s.x += w * v.x; s.y += w * v.y;
                }
            }
            {
                int xi = x0i + 1, yi = y0i + 1;
                if (xi >= 0 && xi < Wl && yi >= 0 && yi < Hl) {
                    float w = wx * wy;
                    float2 v = __half22float2(vlev[(size_t)(yi * Wl + xi) * 128]);
                    s.x += w * v.x; s.y += w * v.y;
                }
            }
            acc.x += a * s.x;
            acc.y += a * s.y;
        }
    }
    out[(size_t)token * 128 + h * 16 + cp] = __floats2half2_rn(acc.x, acc.y);
}

// ---------------- residual add + LayerNorm (optional fp16 aux output) ----------------
template<bool HALF_AUX>
__global__ void add_layernorm(const float* __restrict__ a, const float* __restrict__ b,
                              const float* __restrict__ gamma, const float* __restrict__ beta,
                              float* __restrict__ out, __half* __restrict__ outh) {
    __shared__ float red[8];
    int token = blockIdx.x;
    int c = threadIdx.x;
    float v = a[(size_t)token * D_MODEL + c] + b[(size_t)token * D_MODEL + c];

    float s = v;
    #pragma unroll
    for (int o = 16; o > 0; o >>= 1) s += __shfl_xor_sync(0xffffffffu, s, o);
    if ((c & 31) == 0) red[c >> 5] = s;
    __syncthreads();
    if (c < 8) {
        float t = red[c];
        #pragma unroll
        for (int o = 4; o > 0; o >>= 1) t += __shfl_xor_sync(0xffu, t, o);
        if (c == 0) red[0] = t;
    }
    __syncthreads();
    float mu = red[0] * (1.f / D_MODEL);
    __syncthreads();

    float d = v - mu;
    float ss = d * d;
    #pragma unroll
    for (int o = 16; o > 0; o >>= 1) ss += __shfl_xor_sync(0xffffffffu, ss, o);
    if ((c & 31) == 0) red[c >> 5] = ss;
    __syncthreads();
    if (c < 8) {
        float t = red[c];
        #pragma unroll
        for (int o = 4; o > 0; o >>= 1) t += __shfl_xor_sync(0xffu, t, o);
        if (c == 0) red[0] = t;
    }
    __syncthreads();
    float var = red[0] * (1.f / D_MODEL);
    float inv = rsqrtf(var + 1e-5f);

    float o_ = d * inv * gamma[c] + beta[c];
    out[(size_t)token * D_MODEL + c] = o_;
    if (HALF_AUX) outh[(size_t)token * D_MODEL + c] = __float2half(o_);
}

// ---------------- launch ----------------
extern "C" void kernel_launch(void* const* d_in, const int* in_sizes, int n_in,
                              void* d_out, int out_size) {
    const float* src   = (const float*)d_in[0];
    const float* pos   = (const float*)d_in[1];
    const float* ref   = (const float*)d_in[2];
    const float* W_off = (const float*)d_in[5];
    const float* b_off = (const float*)d_in[6];
    const float* W_att = (const float*)d_in[7];
    const float* b_att = (const float*)d_in[8];
    const float* W_val = (const float*)d_in[9];
    const float* b_val = (const float*)d_in[10];
    const float* W_out = (const float*)d_in[11];
    const float* b_out = (const float*)d_in[12];
    const float* ln1g  = (const float*)d_in[13];
    const float* ln1b  = (const float*)d_in[14];
    const float* W1    = (const float*)d_in[15];
    const float* b1    = (const float*)d_in[16];
    const float* W2    = (const float*)d_in[17];
    const float* b2    = (const float*)d_in[18];
    const float* ln2g  = (const float*)d_in[19];
    const float* ln2b  = (const float*)d_in[20];
    float* out = (float*)d_out;

    float  *oa, *attno, *x, *ffn, *boa;
    __half *valh, *srch, *qh, *samph, *xh, *hh, *wt;
    cudaGetSymbolAddress((void**)&oa,    g_oa);
    cudaGetSymbolAddress((void**)&attno, g_attno);
    cudaGetSymbolAddress((void**)&x,     g_x);
    cudaGetSymbolAddress((void**)&ffn,   g_ffn);
    cudaGetSymbolAddress((void**)&valh,  g_valh);
    cudaGetSymbolAddress((void**)&srch,  g_srch);
    cudaGetSymbolAddress((void**)&qh,    g_qh);
    cudaGetSymbolAddress((void**)&samph, g_samph);
    cudaGetSymbolAddress((void**)&xh,    g_xh);
    cudaGetSymbolAddress((void**)&hh,    g_hh);
    cudaGetSymbolAddress((void**)&wt,    g_wt);
    cudaGetSymbolAddress((void**)&boa,   g_boa);

    const int M = TOKENS;
    const int MB = (M + 127) / 128;
    dim3 thr(256);

    // all weight transposes + bias concat, one launch
    prep_weights<<<736, thr>>>(W_val, W_off, W_att, W_out, W1, W2, b_off, b_att, wt, boa);

    // srch = fp16(src); qh = fp16(src + pos)
    prep_h<<<(M * D_MODEL / 4 + 255) / 256, thr>>>(
        (const float4*)src, (const float4*)pos, (__half2*)srch, (__half2*)qh, M * D_MODEL / 4);

    // GEMMs (fp16 tensor cores)
    gemm_f16<false, true><<<dim3(4, MB), thr, SMEM_BYTES>>>(
        srch, wt + WT_VAL, b_val, valh, M, 256, 256);
    gemm_f16<false, false><<<dim3(6, MB), thr, SMEM_BYTES>>>(
        qh, wt + WT_OA, boa, oa, M, 384, 256);

    // sampler (softmax fused in-register)
    ms_sample_h<<<M / 2, thr>>>((const __half2*)valh, oa, ref, (__half2*)samph);

    gemm_f16<false, false><<<dim3(4, MB), thr, SMEM_BYTES>>>(
        samph, wt + WT_OUT, b_out, attno, M, 256, 256);

    add_layernorm<true><<<M, thr>>>(src, attno, ln1g, ln1b, x, xh);

    gemm_f16<true, true><<<dim3(16, MB), thr, SMEM_BYTES>>>(
        xh, wt + WT_W1, b1, hh, M, 1024, 256);
    gemm_f16<false, false><<<dim3(4, MB), thr, SMEM_BYTES>>>(
        hh, wt + WT_W2, b2, ffn, M, 256, 1024);

    add_layernorm<false><<<M, thr>>>(x, ffn, ln2g, ln2b, out, nullptr);
}

// round 11
// speedup vs baseline: 3.3623x; 1.0245x over previous
#include <cuda_runtime.h>
#include <cuda_fp16.h>
#include <cstdint>
#include <math.h>

// ---------------- static problem shape ----------------
#define BATCH     2
#define S_TOTAL   13294
#define TOKENS    (BATCH * S_TOTAL)     // 26588
#define D_MODEL   256
#define D_FC      1024
#define N_HEADS   8
#define N_LEVELS  4
#define N_POINTS  4
#define D_HEAD    32

__device__ __constant__ int c_H[4]     = {100, 50, 25, 13};
__device__ __constant__ int c_W[4]     = {100, 50, 25, 13};
__device__ __constant__ int c_start[4] = {0, 10000, 12500, 13125};

// ---------------- scratch (no cudaMalloc allowed) ----------------
__device__ float  g_oa     [TOKENS * 384];       // fused [off(256) | attn_logits(128)]
__device__ float  g_attno  [TOKENS * D_MODEL];
__device__ float  g_x      [TOKENS * D_MODEL];
__device__ float  g_ffn    [TOKENS * D_MODEL];
__device__ __half g_valh   [TOKENS * D_MODEL];   // fp16 value projection
__device__ __half g_srch   [TOKENS * D_MODEL];   // fp16 src
__device__ __half g_qh     [TOKENS * D_MODEL];   // fp16 q = src+pos
__device__ __half g_samph  [TOKENS * D_MODEL];   // fp16 sampled
__device__ __half g_xh     [TOKENS * D_MODEL];   // fp16 LN1 out
__device__ __half g_hh     [TOKENS * D_FC];      // fp16 ffn hidden
__device__ __half g_wt     [753664];             // fp16 transposed weights [N][K]
__device__ float  g_boa    [384];                // concat bias off|attn

// offsets in g_wt (halves)
#define WT_VAL 0
#define WT_OA  65536          // 384 x 256
#define WT_OUT 163840         // 256 x 256
#define WT_W1  229376         // 1024 x 256
#define WT_W2  491520         // 256 x 1024

// ---------------- mma fp16 helper ----------------
__device__ __forceinline__ void mma_f16(float& d0, float& d1, float& d2, float& d3,
                                        uint32_t a0, uint32_t a1, uint32_t a2, uint32_t a3,
                                        uint32_t b0, uint32_t b1) {
    asm volatile(
        "mma.sync.aligned.m16n8k16.row.col.f32.f16.f16.f32 "
        "{%0,%1,%2,%3}, {%4,%5,%6,%7}, {%8,%9}, {%0,%1,%2,%3};\n"
        : "+f"(d0), "+f"(d1), "+f"(d2), "+f"(d3)
        : "r"(a0), "r"(a1), "r"(a2), "r"(a3), "r"(b0), "r"(b1));
}

// ---------------- ldmatrix helper ----------------
__device__ __forceinline__ void ldsm4(uint32_t& r0, uint32_t& r1, uint32_t& r2, uint32_t& r3,
                                      uint32_t addr) {
    asm volatile("ldmatrix.sync.aligned.m8n8.x4.shared.b16 {%0,%1,%2,%3}, [%4];\n"
                 : "=r"(r0), "=r"(r1), "=r"(r2), "=r"(r3) : "r"(addr));
}

// ---------------- cp.async helpers ----------------
__device__ __forceinline__ void cp16(uint32_t smem_addr, const void* gmem, bool pred) {
    int sz = pred ? 16 : 0;
    asm volatile("cp.async.cg.shared.global [%0], [%1], 16, %2;\n"
                 :: "r"(smem_addr), "l"(gmem), "r"(sz));
}
__device__ __forceinline__ void cp_commit() {
    asm volatile("cp.async.commit_group;\n");
}

// ---------------- fused weight prep: 5 transposes + bias concat, one launch -------
__global__ void __launch_bounds__(256) prep_weights(
        const float* __restrict__ Wv, const float* __restrict__ Wo,
        const float* __restrict__ Wa, const float* __restrict__ Wu,
        const float* __restrict__ W1, const float* __restrict__ W2,
        const float* __restrict__ b_off, const float* __restrict__ b_att,
        __half* __restrict__ wt, float* __restrict__ boa) {
    const int tid = threadIdx.x;
    const int bx  = blockIdx.x;
    if (bx == 0) {
        boa[tid] = b_off[tid];
        if (tid < 128) boa[256 + tid] = b_att[tid];
    }

    const float* in; __half* out;
    int K, N, rowOff, base, tilesX;
    if      (bx < 64)  { in = Wv; out = wt + WT_VAL; K = 256;  N = 256;  rowOff = 0;   base = 0;   tilesX = 8;  }
    else if (bx < 128) { in = Wo; out = wt + WT_OA;  K = 256;  N = 256;  rowOff = 0;   base = 64;  tilesX = 8;  }
    else if (bx < 160) { in = Wa; out = wt + WT_OA;  K = 256;  N = 128;  rowOff = 256; base = 128; tilesX = 4;  }
    else if (bx < 224) { in = Wu; out = wt + WT_OUT; K = 256;  N = 256;  rowOff = 0;   base = 160; tilesX = 8;  }
    else if (bx < 480) { in = W1; out = wt + WT_W1;  K = 256;  N = 1024; rowOff = 0;   base = 224; tilesX = 32; }
    else               { in = W2; out = wt + WT_W2;  K = 1024; N = 256;  rowOff = 0;   base = 480; tilesX = 8;  }

    const int local = bx - base;
    const int n0 = (local % tilesX) * 32;
    const int k0 = (local / tilesX) * 32;

    __shared__ float t[32][33];
    const int tx = tid & 31, ty = tid >> 5;
    #pragma unroll
    for (int i = 0; i < 32; i += 8)
        t[ty + i][tx] = in[(size_t)(k0 + ty + i) * N + n0 + tx];
    __syncthreads();
    #pragma unroll
    for (int i = 0; i < 32; i += 8)
        out[(size_t)(rowOff + n0 + ty + i) * K + k0 + tx] = __float2half(t[tx][ty + i]);
}

// ---------------- fused: srch = fp16(src); qh = fp16(src + pos) ----------------
__global__ void prep_h(const float4* __restrict__ src, const float4* __restrict__ pos,
                       __half2* __restrict__ srch, __half2* __restrict__ qh, int n4) {
    int i = blockIdx.x * blockDim.x + threadIdx.x;
    if (i < n4) {
        float4 s = src[i], p = pos[i];
        srch[2 * i]     = __floats2half2_rn(s.x, s.y);
        srch[2 * i + 1] = __floats2half2_rn(s.z, s.w);
        qh[2 * i]       = __floats2half2_rn(s.x + p.x, s.y + p.y);
        qh[2 * i + 1]   = __floats2half2_rn(s.z + p.z, s.w + p.w);
    }
}

// ---------------- fp16 tensor-core GEMM, cp.async 3-stage + ldmatrix ----------------
// C[M,N] = A[M,K](fp16) @ Bt[N,K](fp16, row=n) + bias (+ReLU).
// BM=128, BN=64, BK=32, 256 threads (8 warps, 4x2), warp tile 32x32, m16n8k16.
// smem rows = 40 halves (80B) -> conflict-free for cp.async stores and ldmatrix.
#define AROW_W 20
#define A_WORDS (128 * AROW_W)
#define B_WORDS (64 * AROW_W)
#define A_BYTES (A_WORDS * 4)
#define B_BYTES (B_WORDS * 4)
#define SMEM_BYTES (3 * (A_WORDS + B_WORDS) * 4)   // 46080

template<bool RELU, bool HALF_OUT>
__global__ void __launch_bounds__(256) gemm_f16(
        const __half* __restrict__ A, const __half* __restrict__ Bt,
        const float* __restrict__ bias, void* __restrict__ Cv,
        int M, int N, int K) {
    extern __shared__ uint32_t smem[];
    uint32_t* As = smem;
    uint32_t* Bs = smem + 3 * A_WORDS;
    const uint32_t sAs = (uint32_t)__cvta_generic_to_shared(As);
    const uint32_t sBs = (uint32_t)__cvta_generic_to_shared(Bs);

    const int tid  = threadIdx.x;
    const int lane = tid & 31;
    const int warp = tid >> 5;
    const int wm   = warp & 3;
    const int wn   = warp >> 2;
    const int row0 = blockIdx.y * 128;
    const int col0 = blockIdx.x * 64;

    const int ntiles = K / 32;

    auto issue = [&](int kt, int st) {
        const int kg = kt * 32;
        const uint32_t aB = sAs + st * A_BYTES;
        const uint32_t bB = sBs + st * B_BYTES;
        const int chunk = tid & 3;
        #pragma unroll
        for (int i = 0; i < 2; i++) {
            int m = (tid >> 2) + i * 64;
            int gr = row0 + m;
            bool ok = gr < M;
            const __half* g = A + (size_t)(ok ? gr : 0) * K + kg + chunk * 8;
            cp16(aB + m * 80 + chunk * 16, g, ok);
        }
        {
            int n = tid >> 2;
            const __half* g = Bt + (size_t)(col0 + n) * K + kg + chunk * 8;
            cp16(bB + n * 80 + chunk * 16, g, true);
        }
        cp_commit();
    };

    float acc[2][4][4];
    #pragma unroll
    for (int t = 0; t < 2; t++)
        #pragma unroll
        for (int n = 0; n < 4; n++)
            #pragma unroll
            for (int j = 0; j < 4; j++) acc[t][n][j] = 0.f;

    issue(0, 0);
    if (ntiles > 1) issue(1, 1);

    // ldmatrix per-lane base addresses (bytes within a stage)
    // A x4 (t-th m16 tile): rows wm*32 + t*16 + (lane&15); 16B chunk = lane>>4
    const uint32_t aAddr0 = (uint32_t)((wm * 32 + (lane & 15)) * 80 + (lane >> 4) * 16);
    // B x4 (j-th pair of n8 tiles): rows wn*32 + j*16 + ((lane>>4)&1)*8 + (lane&7);
    // 16B chunk = (lane>>3)&1
    const uint32_t bAddr0 = (uint32_t)((wn * 32 + ((lane >> 4) & 1) * 8 + (lane & 7)) * 80
                                       + ((lane >> 3) & 1) * 16);

    for (int kt = 0; kt < ntiles; kt++) {
        if (kt + 1 < ntiles) { asm volatile("cp.async.wait_group 1;\n"); }
        else                 { asm volatile("cp.async.wait_group 0;\n"); }
        __syncthreads();
        if (kt + 2 < ntiles) issue(kt + 2, (kt + 2) % 3);

        const int st = kt % 3;
        const uint32_t aBase = sAs + st * A_BYTES + aAddr0;
        const uint32_t bBase = sBs + st * B_BYTES + bAddr0;

        #pragma unroll
        for (int ks = 0; ks < 2; ks++) {
            uint32_t af[2][4];
            #pragma unroll
            for (int t = 0; t < 2; t++)
                ldsm4(af[t][0], af[t][1], af[t][2], af[t][3],
                      aBase + t * (16 * 80) + ks * 32);
            uint32_t bf[4][2];
            #pragma unroll
            for (int j = 0; j < 2; j++)
                ldsm4(bf[2 * j][0], bf[2 * j][1], bf[2 * j + 1][0], bf[2 * j + 1][1],
                      bBase + j * (16 * 80) + ks * 32);
            #pragma unroll
            for (int t = 0; t < 2; t++)
                #pragma unroll
                for (int n = 0; n < 4; n++)
                    mma_f16(acc[t][n][0], acc[t][n][1], acc[t][n][2], acc[t][n][3],
                            af[t][0], af[t][1], af[t][2], af[t][3],
                            bf[n][0], bf[n][1]);
        }
    }

    // ---- epilogue ----
    const int q = lane & 3;
    const int r = lane >> 2;
    #pragma unroll
    for (int t = 0; t < 2; t++) {
        #pragma unroll
        for (int n = 0; n < 4; n++) {
            int gr = row0 + wm * 32 + t * 16 + r;
            int gc = col0 + wn * 32 + n * 8 + 2 * q;
            float b0 = bias[gc], b1 = bias[gc + 1];
            #pragma unroll
            for (int half_ = 0; half_ < 2; half_++) {
                int grr = gr + 8 * half_;
                if (grr >= M) continue;
                float v0 = acc[t][n][2 * half_]     + b0;
                float v1 = acc[t][n][2 * half_ + 1] + b1;
                if (RELU) { v0 = fmaxf(v0, 0.f); v1 = fmaxf(v1, 0.f); }
                if (HALF_OUT) {
                    __half2* C = (__half2*)Cv;
                    C[((size_t)grr * N + gc) >> 1] = __floats2half2_rn(v0, v1);
                } else {
                    float* C = (float*)Cv;
                    C[(size_t)grr * N + gc]     = v0;
                    C[(size_t)grr * N + gc + 1] = v1;
                }
            }
        }
    }
}

// ---------------- multi-scale deformable sampling, fused softmax -----------------
__global__ void ms_sample_h(const __half2* __restrict__ valh, const float* __restrict__ oa,
                            const float* __restrict__ ref, __half2* __restrict__ out) {
    const int warp = threadIdx.x >> 5;
    const int lane = threadIdx.x & 31;
    const int token = blockIdx.x * 2 + (warp >> 2);
    const int h  = ((warp & 3) << 1) + (lane >> 4);   // head 0..7
    const int cp = lane & 15;                         // channel pair 0..15
    const int b = token / S_TOTAL;

    const float* refp  = ref + (size_t)token * (N_LEVELS * 2);
    const float* offp  = oa  + (size_t)token * 384 + h * 32;
    const float* attnp = oa  + (size_t)token * 384 + 256 + h * 16;
    const __half2* vbase = valh + (size_t)b * S_TOTAL * 128 + h * 16 + cp;

    // ---- in-register softmax over the 16-lane group ----
    float logit = attnp[cp];
    float m_ = logit;
    #pragma unroll
    for (int o = 8; o > 0; o >>= 1) m_ = fmaxf(m_, __shfl_xor_sync(0xffffffffu, m_, o));
    float e = __expf(logit - m_);
    float ssum = e;
    #pragma unroll
    for (int o = 8; o > 0; o >>= 1) ssum += __shfl_xor_sync(0xffffffffu, ssum, o);
    const float aval = e / ssum;
    const int grp = lane & 16;

    float2 acc = make_float2(0.f, 0.f);
    #pragma unroll
    for (int l = 0; l < N_LEVELS; l++) {
        const int Hl = c_H[l], Wl = c_W[l];
        const float fH = (float)Hl, fW = (float)Wl;
        const float rx = refp[l * 2 + 0];
        const float ry = refp[l * 2 + 1];
        const __half2* vlev = vbase + (size_t)c_start[l] * 128;
        #pragma unroll
        for (int p = 0; p < N_POINTS; p++) {
            float ox = offp[l * 8 + p * 2 + 0];
            float oy = offp[l * 8 + p * 2 + 1];
            float px = (rx + ox / fW) * fW - 0.5f;
            float py = (ry + oy / fH) * fH - 0.5f;
            float x0 = floorf(px), y0 = floorf(py);
            float wx = px - x0, wy = py - y0;
            int x0i = (int)x0, y0i = (int)y0;
            float a = __shfl_sync(0xffffffffu, aval, grp | (l * 4 + p));

            float2 s = make_float2(0.f, 0.f);
            {
                if (x0i >= 0 && x0i < Wl && y0i >= 0 && y0i < Hl) {
                    float w = (1.f - wx) * (1.f - wy);
                    float2 v = __half22float2(vlev[(size_t)(y0i * Wl + x0i) * 128]);
                    s.x += w * v.x; s.y += w * v.y;
                }
            }
            {
                int xi = x0i + 1;
                if (xi >= 0 && xi < Wl && y0i >= 0 && y0i < Hl) {
                    float w = wx * (1.f - wy);
                    float2 v = __half22float2(vlev[(size_t)(y0i * Wl + xi) * 128]);
                    s.x += w * v.x; s.y += w * v.y;
                }
            }
            {
                int yi = y0i + 1;
                if (x0i >= 0 && x0i < Wl && yi >= 0 && yi < Hl) {
                    float w = (1.f - wx) * wy;
                    float2 v = __half22float2(vlev[(size_t)(yi * Wl + x0i) * 128]);
                    s.x += w * v.x; s.y += w * v.y;
                }
            }
            {
                int xi = x0i + 1, yi = y0i + 1;
                if (xi >= 0 && xi < Wl && yi >= 0 && yi < Hl) {
                    float w = wx * wy;
                    float2 v = __half22float2(vlev[(size_t)(yi * Wl + xi) * 128]);
                    s.x += w * v.x; s.y += w * v.y;
                }
            }
            acc.x += a * s.x;
            acc.y += a * s.y;
        }
    }
    out[(size_t)token * 128 + h * 16 + cp] = __floats2half2_rn(acc.x, acc.y);
}

// ---------------- residual add + LayerNorm (optional fp16 aux output) ----------------
template<bool HALF_AUX>
__global__ void add_layernorm(const float* __restrict__ a, const float* __restrict__ b,
                              const float* __restrict__ gamma, const float* __restrict__ beta,
                              float* __restrict__ out, __half* __restrict__ outh) {
    __shared__ float red[8];
    int token = blockIdx.x;
    int c = threadIdx.x;
    float v = a[(size_t)token * D_MODEL + c] + b[(size_t)token * D_MODEL + c];

    float s = v;
    #pragma unroll
    for (int o = 16; o > 0; o >>= 1) s += __shfl_xor_sync(0xffffffffu, s, o);
    if ((c & 31) == 0) red[c >> 5] = s;
    __syncthreads();
    if (c < 8) {
        float t = red[c];
        #pragma unroll
        for (int o = 4; o > 0; o >>= 1) t += __shfl_xor_sync(0xffu, t, o);
        if (c == 0) red[0] = t;
    }
    __syncthreads();
    float mu = red[0] * (1.f / D_MODEL);
    __syncthreads();

    float d = v - mu;
    float ss = d * d;
    #pragma unroll
    for (int o = 16; o > 0; o >>= 1) ss += __shfl_xor_sync(0xffffffffu, ss, o);
    if ((c & 31) == 0) red[c >> 5] = ss;
    __syncthreads();
    if (c < 8) {
        float t = red[c];
        #pragma unroll
        for (int o = 4; o > 0; o >>= 1) t += __shfl_xor_sync(0xffu, t, o);
        if (c == 0) red[0] = t;
    }
    __syncthreads();
    float var = red[0] * (1.f / D_MODEL);
    float inv = rsqrtf(var + 1e-5f);

    float o_ = d * inv * gamma[c] + beta[c];
    out[(size_t)token * D_MODEL + c] = o_;
    if (HALF_AUX) outh[(size_t)token * D_MODEL + c] = __float2half(o_);
}

// ---------------- launch ----------------
extern "C" void kernel_launch(void* const* d_in, const int* in_sizes, int n_in,
                              void* d_out, int out_size) {
    const float* src   = (const float*)d_in[0];
    const float* pos   = (const float*)d_in[1];
    const float* ref   = (const float*)d_in[2];
    const float* W_off = (const float*)d_in[5];
    const float* b_off = (const float*)d_in[6];
    const float* W_att = (const float*)d_in[7];
    const float* b_att = (const float*)d_in[8];
    const float* W_val = (const float*)d_in[9];
    const float* b_val = (const float*)d_in[10];
    const float* W_out = (const float*)d_in[11];
    const float* b_out = (const float*)d_in[12];
    const float* ln1g  = (const float*)d_in[13];
    const float* ln1b  = (const float*)d_in[14];
    const float* W1    = (const float*)d_in[15];
    const float* b1    = (const float*)d_in[16];
    const float* W2    = (const float*)d_in[17];
    const float* b2    = (const float*)d_in[18];
    const float* ln2g  = (const float*)d_in[19];
    const float* ln2b  = (const float*)d_in[20];
    float* out = (float*)d_out;

    float  *oa, *attno, *x, *ffn, *boa;
    __half *valh, *srch, *qh, *samph, *xh, *hh, *wt;
    cudaGetSymbolAddress((void**)&oa,    g_oa);
    cudaGetSymbolAddress((void**)&attno, g_attno);
    cudaGetSymbolAddress((void**)&x,     g_x);
    cudaGetSymbolAddress((void**)&ffn,   g_ffn);
    cudaGetSymbolAddress((void**)&valh,  g_valh);
    cudaGetSymbolAddress((void**)&srch,  g_srch);
    cudaGetSymbolAddress((void**)&qh,    g_qh);
    cudaGetSymbolAddress((void**)&samph, g_samph);
    cudaGetSymbolAddress((void**)&xh,    g_xh);
    cudaGetSymbolAddress((void**)&hh,    g_hh);
    cudaGetSymbolAddress((void**)&wt,    g_wt);
    cudaGetSymbolAddress((void**)&boa,   g_boa);

    const int M = TOKENS;
    const int MB = (M + 127) / 128;
    dim3 thr(256);

    // all weight transposes + bias concat, one launch
    prep_weights<<<736, thr>>>(W_val, W_off, W_att, W_out, W1, W2, b_off, b_att, wt, boa);

    // srch = fp16(src); qh = fp16(src + pos)
    prep_h<<<(M * D_MODEL / 4 + 255) / 256, thr>>>(
        (const float4*)src, (const float4*)pos, (__half2*)srch, (__half2*)qh, M * D_MODEL / 4);

    // GEMMs (fp16 tensor cores, ldmatrix fragments)
    gemm_f16<false, true><<<dim3(4, MB), thr, SMEM_BYTES>>>(
        srch, wt + WT_VAL, b_val, valh, M, 256, 256);
    gemm_f16<false, false><<<dim3(6, MB), thr, SMEM_BYTES>>>(
        qh, wt + WT_OA, boa, oa, M, 384, 256);

    // sampler (softmax fused in-register)
    ms_sample_h<<<M / 2, thr>>>((const __half2*)valh, oa, ref, (__half2*)samph);

    gemm_f16<false, false><<<dim3(4, MB), thr, SMEM_BYTES>>>(
        samph, wt + WT_OUT, b_out, attno, M, 256, 256);

    add_layernorm<true><<<M, thr>>>(src, attno, ln1g, ln1b, x, xh);

    gemm_f16<true, true><<<dim3(16, MB), thr, SMEM_BYTES>>>(
        xh, wt + WT_W1, b1, hh, M, 1024, 256);
    gemm_f16<false, false><<<dim3(4, MB), thr, SMEM_BYTES>>>(
        hh, wt + WT_W2, b2, ffn, M, 256, 1024);

    add_layernorm<false><<<M, thr>>>(x, ffn, ln2g, ln2b, out, nullptr);
}

// round 13
// speedup vs baseline: 3.5804x; 1.0648x over previous
#include <cuda_runtime.h>
#include <cuda_fp16.h>
#include <cstdint>
#include <math.h>

// ---------------- static problem shape ----------------
#define BATCH     2
#define S_TOTAL   13294
#define TOKENS    (BATCH * S_TOTAL)     // 26588
#define D_MODEL   256
#define D_FC      1024
#define N_HEADS   8
#define N_LEVELS  4
#define N_POINTS  4
#define D_HEAD    32

__device__ __constant__ int c_H[4]     = {100, 50, 25, 13};
__device__ __constant__ int c_W[4]     = {100, 50, 25, 13};
__device__ __constant__ int c_start[4] = {0, 10000, 12500, 13125};

// ---------------- scratch (no cudaMalloc allowed) ----------------
__device__ float  g_oa     [TOKENS * 384];       // fused [off(256) | attn_logits(128)]
__device__ float  g_attno  [TOKENS * D_MODEL];
__device__ float  g_x      [TOKENS * D_MODEL];
__device__ float  g_ffn    [TOKENS * D_MODEL];
__device__ __half g_valh   [TOKENS * D_MODEL];   // fp16 value projection
__device__ __half g_srch   [TOKENS * D_MODEL];   // fp16 src
__device__ __half g_qh     [TOKENS * D_MODEL];   // fp16 q = src+pos
__device__ __half g_samph  [TOKENS * D_MODEL];   // fp16 sampled
__device__ __half g_xh     [TOKENS * D_MODEL];   // fp16 LN1 out
__device__ __half g_hh     [TOKENS * D_FC];      // fp16 ffn hidden
__device__ __half g_wt     [753664];             // fp16 transposed weights [N][K]
__device__ float  g_boa    [384];                // concat bias off|attn

// offsets in g_wt (halves)
#define WT_VAL 0
#define WT_OA  65536          // 384 x 256
#define WT_OUT 163840         // 256 x 256
#define WT_W1  229376         // 1024 x 256
#define WT_W2  491520         // 256 x 1024

// ---------------- mma fp16 helper ----------------
__device__ __forceinline__ void mma_f16(float& d0, float& d1, float& d2, float& d3,
                                        uint32_t a0, uint32_t a1, uint32_t a2, uint32_t a3,
                                        uint32_t b0, uint32_t b1) {
    asm volatile(
        "mma.sync.aligned.m16n8k16.row.col.f32.f16.f16.f32 "
        "{%0,%1,%2,%3}, {%4,%5,%6,%7}, {%8,%9}, {%0,%1,%2,%3};\n"
        : "+f"(d0), "+f"(d1), "+f"(d2), "+f"(d3)
        : "r"(a0), "r"(a1), "r"(a2), "r"(a3), "r"(b0), "r"(b1));
}

// ---------------- ldmatrix helper ----------------
__device__ __forceinline__ void ldsm4(uint32_t& r0, uint32_t& r1, uint32_t& r2, uint32_t& r3,
                                      uint32_t addr) {
    asm volatile("ldmatrix.sync.aligned.m8n8.x4.shared.b16 {%0,%1,%2,%3}, [%4];\n"
                 : "=r"(r0), "=r"(r1), "=r"(r2), "=r"(r3) : "r"(addr));
}

// ---------------- cp.async helpers ----------------
__device__ __forceinline__ void cp16p(uint32_t smem_addr, const void* gmem, bool pred) {
    int sz = pred ? 16 : 0;
    asm volatile("cp.async.cg.shared.global [%0], [%1], 16, %2;\n"
                 :: "r"(smem_addr), "l"(gmem), "r"(sz));
}
__device__ __forceinline__ void cp16(uint32_t smem_addr, const void* gmem) {
    asm volatile("cp.async.cg.shared.global [%0], [%1], 16;\n"
                 :: "r"(smem_addr), "l"(gmem));
}

// ---------------- fused weight prep: 5 transposes + bias concat, one launch -------
__global__ void __launch_bounds__(256) prep_weights(
        const float* __restrict__ Wv, const float* __restrict__ Wo,
        const float* __restrict__ Wa, const float* __restrict__ Wu,
        const float* __restrict__ W1, const float* __restrict__ W2,
        const float* __restrict__ b_off, const float* __restrict__ b_att,
        __half* __restrict__ wt, float* __restrict__ boa) {
    const int tid = threadIdx.x;
    const int bx  = blockIdx.x;
    if (bx == 0) {
        boa[tid] = b_off[tid];
        if (tid < 128) boa[256 + tid] = b_att[tid];
    }

    const float* in; __half* out;
    int K, N, rowOff, base, tilesX;
    if      (bx < 64)  { in = Wv; out = wt + WT_VAL; K = 256;  N = 256;  rowOff = 0;   base = 0;   tilesX = 8;  }
    else if (bx < 128) { in = Wo; out = wt + WT_OA;  K = 256;  N = 256;  rowOff = 0;   base = 64;  tilesX = 8;  }
    else if (bx < 160) { in = Wa; out = wt + WT_OA;  K = 256;  N = 128;  rowOff = 256; base = 128; tilesX = 4;  }
    else if (bx < 224) { in = Wu; out = wt + WT_OUT; K = 256;  N = 256;  rowOff = 0;   base = 160; tilesX = 8;  }
    else if (bx < 480) { in = W1; out = wt + WT_W1;  K = 256;  N = 1024; rowOff = 0;   base = 224; tilesX = 32; }
    else               { in = W2; out = wt + WT_W2;  K = 1024; N = 256;  rowOff = 0;   base = 480; tilesX = 8;  }

    const int local = bx - base;
    const int n0 = (local % tilesX) * 32;
    const int k0 = (local / tilesX) * 32;

    __shared__ float t[32][33];
    const int tx = tid & 31, ty = tid >> 5;
    #pragma unroll
    for (int i = 0; i < 32; i += 8)
        t[ty + i][tx] = in[(size_t)(k0 + ty + i) * N + n0 + tx];
    __syncthreads();
    #pragma unroll
    for (int i = 0; i < 32; i += 8)
        out[(size_t)(rowOff + n0 + ty + i) * K + k0 + tx] = __float2half(t[tx][ty + i]);
}

// ---------------- fused: srch = fp16(src); qh = fp16(src + pos) ----------------
__global__ void prep_h(const float4* __restrict__ src, const float4* __restrict__ pos,
                       __half2* __restrict__ srch, __half2* __restrict__ qh, int n4) {
    int i = blockIdx.x * blockDim.x + threadIdx.x;
    if (i < n4) {
        float4 s = src[i], p = pos[i];
        srch[2 * i]     = __floats2half2_rn(s.x, s.y);
        srch[2 * i + 1] = __floats2half2_rn(s.z, s.w);
        qh[2 * i]       = __floats2half2_rn(s.x + p.x, s.y + p.y);
        qh[2 * i + 1]   = __floats2half2_rn(s.z + p.z, s.w + p.w);
    }
}

// ---------------- fp16 tensor-core GEMM, 2-stage cp.async, BK=64, ldmatrix --------
// C[M,N] = A[M,K](fp16) @ Bt[N,K](fp16, row=n) + bias (+ReLU).
// BM=128, BN=64, BK=64, 256 threads (8 warps, 4x2), warp tile 32x32, m16n8k16.
// smem row pitch = 144B (72 halves): conflict-free for cp.async stores and ldmatrix.
#define AROW_B  144
#define A_STAGE (128 * AROW_B)            // 18432 B
#define B_STAGE (64 * AROW_B)             // 9216 B
#define STAGE_B (A_STAGE + B_STAGE)       // 27648 B
#define SMEM_BYTES (2 * STAGE_B)          // 55296 B

template<bool RELU, bool HALF_OUT>
__global__ void __launch_bounds__(256) gemm_f16(
        const __half* __restrict__ A, const __half* __restrict__ Bt,
        const float* __restrict__ bias, void* __restrict__ Cv,
        int M, int N, int K) {
    extern __shared__ uint32_t smem[];
    const uint32_t sS = (uint32_t)__cvta_generic_to_shared(smem);

    const int tid  = threadIdx.x;
    const int lane = tid & 31;
    const int warp = tid >> 5;
    const int wm   = warp & 3;
    const int wn   = warp >> 2;
    const int row0 = blockIdx.y * 128;
    const int col0 = blockIdx.x * 64;

    const int ntiles = K >> 6;            // BK=64

    auto issue = [&](int kt, int st) {
        const int kg = kt << 6;
        const uint32_t aB = sS + st * STAGE_B;
        const uint32_t bB = aB + A_STAGE;
        #pragma unroll
        for (int i = 0; i < 4; i++) {
            int cid = tid + (i << 8);
            int m = cid >> 3;
            int c = cid & 7;
            int gr = row0 + m;
            bool ok = gr < M;
            const __half* g = A + (size_t)(ok ? gr : 0) * K + kg + c * 8;
            cp16p(aB + m * AROW_B + c * 16, g, ok);
        }
        #pragma unroll
        for (int i = 0; i < 2; i++) {
            int cid = tid + (i << 8);
            int n = cid >> 3;
            int c = cid & 7;
            const __half* g = Bt + (size_t)(col0 + n) * K + kg + c * 8;
            cp16(bB + n * AROW_B + c * 16, g);
        }
        asm volatile("cp.async.commit_group;\n");
    };

    float acc[2][4][4];
    #pragma unroll
    for (int t = 0; t < 2; t++)
        #pragma unroll
        for (int n = 0; n < 4; n++)
            #pragma unroll
            for (int j = 0; j < 4; j++) acc[t][n][j] = 0.f;

    issue(0, 0);

    // per-lane ldmatrix base offsets (bytes within a stage)
    const uint32_t aOff = (uint32_t)((wm * 32 + (lane & 15)) * AROW_B + (lane >> 4) * 16);
    const uint32_t bOff = (uint32_t)((wn * 32 + ((lane >> 4) & 1) * 8 + (lane & 7)) * AROW_B
                                     + ((lane >> 3) & 1) * 16);

    for (int kt = 0; kt < ntiles; kt++) {
        asm volatile("cp.async.wait_group 0;\n");
        __syncthreads();
        if (kt + 1 < ntiles) issue(kt + 1, (kt + 1) & 1);

        const int st = kt & 1;
        const uint32_t aBase = sS + st * STAGE_B + aOff;
        const uint32_t bBase = sS + st * STAGE_B + A_STAGE + bOff;

        #pragma unroll
        for (int ks = 0; ks < 4; ks++) {
            uint32_t af[2][4];
            #pragma unroll
            for (int t = 0; t < 2; t++)
                ldsm4(af[t][0], af[t][1], af[t][2], af[t][3],
                      aBase + t * (16 * AROW_B) + ks * 32);
            uint32_t bf[4][2];
            #pragma unroll
            for (int j = 0; j < 2; j++)
                ldsm4(bf[2 * j][0], bf[2 * j][1], bf[2 * j + 1][0], bf[2 * j + 1][1],
                      bBase + j * (16 * AROW_B) + ks * 32);
            #pragma unroll
            for (int t = 0; t < 2; t++)
                #pragma unroll
                for (int n = 0; n < 4; n++)
                    mma_f16(acc[t][n][0], acc[t][n][1], acc[t][n][2], acc[t][n][3],
                            af[t][0], af[t][1], af[t][2], af[t][3],
                            bf[n][0], bf[n][1]);
        }
    }

    // ---- epilogue ----
    const int q = lane & 3;
    const int r = lane >> 2;
    #pragma unroll
    for (int t = 0; t < 2; t++) {
        #pragma unroll
        for (int n = 0; n < 4; n++) {
            int gr = row0 + wm * 32 + t * 16 + r;
            int gc = col0 + wn * 32 + n * 8 + 2 * q;
            float b0 = bias[gc], b1 = bias[gc + 1];
            #pragma unroll
            for (int half_ = 0; half_ < 2; half_++) {
                int grr = gr + 8 * half_;
                if (grr >= M) continue;
                float v0 = acc[t][n][2 * half_]     + b0;
                float v1 = acc[t][n][2 * half_ + 1] + b1;
                if (RELU) { v0 = fmaxf(v0, 0.f); v1 = fmaxf(v1, 0.f); }
                if (HALF_OUT) {
                    __half2* C = (__half2*)Cv;
                    C[((size_t)grr * N + gc) >> 1] = __floats2half2_rn(v0, v1);
                } else {
                    float* C = (float*)Cv;
                    C[(size_t)grr * N + gc]     = v0;
                    C[(size_t)grr * N + gc + 1] = v1;
                }
            }
        }
    }
}

// ---------------- multi-scale deformable sampling, fused softmax -----------------
__global__ void ms_sample_h(const __half2* __restrict__ valh, const float* __restrict__ oa,
                            const float* __restrict__ ref, __half2* __restrict__ out) {
    const int warp = threadIdx.x >> 5;
    const int lane = threadIdx.x & 31;
    const int token = blockIdx.x * 2 + (warp >> 2);
    const int h  = ((warp & 3) << 1) + (lane >> 4);   // head 0..7
    const int cp = lane & 15;                         // channel pair 0..15
    const int b = token / S_TOTAL;

    const float* refp  = ref + (size_t)token * (N_LEVELS * 2);
    const float* offp  = oa  + (size_t)token * 384 + h * 32;
    const float* attnp = oa  + (size_t)token * 384 + 256 + h * 16;
    const __half2* vbase = valh + (size_t)b * S_TOTAL * 128 + h * 16 + cp;

    // ---- in-register softmax over the 16-lane group ----
    float logit = attnp[cp];
    float m_ = logit;
    #pragma unroll
    for (int o = 8; o > 0; o >>= 1) m_ = fmaxf(m_, __shfl_xor_sync(0xffffffffu, m_, o));
    float e = __expf(logit - m_);
    float ssum = e;
    #pragma unroll
    for (int o = 8; o > 0; o >>= 1) ssum += __shfl_xor_sync(0xffffffffu, ssum, o);
    const float aval = e / ssum;
    const int grp = lane & 16;

    float2 acc = make_float2(0.f, 0.f);
    #pragma unroll
    for (int l = 0; l < N_LEVELS; l++) {
        const int Hl = c_H[l], Wl = c_W[l];
        const float fH = (float)Hl, fW = (float)Wl;
        const float rx = refp[l * 2 + 0];
        const float ry = refp[l * 2 + 1];
        const __half2* vlev = vbase + (size_t)c_start[l] * 128;
        #pragma unroll
        for (int p = 0; p < N_POINTS; p++) {
            float ox = offp[l * 8 + p * 2 + 0];
            float oy = offp[l * 8 + p * 2 + 1];
            float px = (rx + ox / fW) * fW - 0.5f;
            float py = (ry + oy / fH) * fH - 0.5f;
            float x0 = floorf(px), y0 = floorf(py);
            float wx = px - x0, wy = py - y0;
            int x0i = (int)x0, y0i = (int)y0;
            float a = __shfl_sync(0xffffffffu, aval, grp | (l * 4 + p));

            float2 s = make_float2(0.f, 0.f);
            {
                if (x0i >= 0 && x0i < Wl && y0i >= 0 && y0i < Hl) {
                    float w = (1.f - wx) * (1.f - wy);
                    float2 v = __half22float2(vlev[(size_t)(y0i * Wl + x0i) * 128]);
                    s.x += w * v.x; s.y += w * v.y;
                }
            }
            {
                int xi = x0i + 1;
                if (xi >= 0 && xi < Wl && y0i >= 0 && y0i < Hl) {
                    float w = wx * (1.f - wy);
                    float2 v = __half22float2(vlev[(size_t)(y0i * Wl + xi) * 128]);
                    s.x += w * v.x; s.y += w * v.y;
                }
            }
            {
                int yi = y0i + 1;
                if (x0i >= 0 && x0i < Wl && yi >= 0 && yi < Hl) {
                    float w = (1.f - wx) * wy;
                    float2 v = __half22float2(vlev[(size_t)(yi * Wl + x0i) * 128]);
                    s.x += w * v.x; s.y += w * v.y;
                }
            }
            {
                int xi = x0i + 1, yi = y0i + 1;
                if (xi >= 0 && xi < Wl && yi >= 0 && yi < Hl) {
                    float w = wx * wy;
                    float2 v = __half22float2(vlev[(size_t)(yi * Wl + xi) * 128]);
                    s.x += w * v.x; s.y += w * v.y;
                }
            }
            acc.x += a * s.x;
            acc.y += a * s.y;
        }
    }
    out[(size_t)token * 128 + h * 16 + cp] = __floats2half2_rn(acc.x, acc.y);
}

// ---------------- residual add + LayerNorm (optional fp16 aux output) ----------------
template<bool HALF_AUX>
__global__ void add_layernorm(const float* __restrict__ a, const float* __restrict__ b,
                              const float* __restrict__ gamma, const float* __restrict__ beta,
                              float* __restrict__ out, __half* __restrict__ outh) {
    __shared__ float red[8];
    int token = blockIdx.x;
    int c = threadIdx.x;
    float v = a[(size_t)token * D_MODEL + c] + b[(size_t)token * D_MODEL + c];

    float s = v;
    #pragma unroll
    for (int o = 16; o > 0; o >>= 1) s += __shfl_xor_sync(0xffffffffu, s, o);
    if ((c & 31) == 0) red[c >> 5] = s;
    __syncthreads();
    if (c < 8) {
        float t = red[c];
        #pragma unroll
        for (int o = 4; o > 0; o >>= 1) t += __shfl_xor_sync(0xffu, t, o);
        if (c == 0) red[0] = t;
    }
    __syncthreads();
    float mu = red[0] * (1.f / D_MODEL);
    __syncthreads();

    float d = v - mu;
    float ss = d * d;
    #pragma unroll
    for (int o = 16; o > 0; o >>= 1) ss += __shfl_xor_sync(0xffffffffu, ss, o);
    if ((c & 31) == 0) red[c >> 5] = ss;
    __syncthreads();
    if (c < 8) {
        float t = red[c];
        #pragma unroll
        for (int o = 4; o > 0; o >>= 1) t += __shfl_xor_sync(0xffu, t, o);
        if (c == 0) red[0] = t;
    }
    __syncthreads();
    float var = red[0] * (1.f / D_MODEL);
    float inv = rsqrtf(var + 1e-5f);

    float o_ = d * inv * gamma[c] + beta[c];
    out[(size_t)token * D_MODEL + c] = o_;
    if (HALF_AUX) outh[(size_t)token * D_MODEL + c] = __float2half(o_);
}

// ---------------- launch ----------------
extern "C" void kernel_launch(void* const* d_in, const int* in_sizes, int n_in,
                              void* d_out, int out_size) {
    const float* src   = (const float*)d_in[0];
    const float* pos   = (const float*)d_in[1];
    const float* ref   = (const float*)d_in[2];
    const float* W_off = (const float*)d_in[5];
    const float* b_off = (const float*)d_in[6];
    const float* W_att = (const float*)d_in[7];
    const float* b_att = (const float*)d_in[8];
    const float* W_val = (const float*)d_in[9];
    const float* b_val = (const float*)d_in[10];
    const float* W_out = (const float*)d_in[11];
    const float* b_out = (const float*)d_in[12];
    const float* ln1g  = (const float*)d_in[13];
    const float* ln1b  = (const float*)d_in[14];
    const float* W1    = (const float*)d_in[15];
    const float* b1    = (const float*)d_in[16];
    const float* W2    = (const float*)d_in[17];
    const float* b2    = (const float*)d_in[18];
    const float* ln2g  = (const float*)d_in[19];
    const float* ln2b  = (const float*)d_in[20];
    float* out = (float*)d_out;

    float  *oa, *attno, *x, *ffn, *boa;
    __half *valh, *srch, *qh, *samph, *xh, *hh, *wt;
    cudaGetSymbolAddress((void**)&oa,    g_oa);
    cudaGetSymbolAddress((void**)&attno, g_attno);
    cudaGetSymbolAddress((void**)&x,     g_x);
    cudaGetSymbolAddress((void**)&ffn,   g_ffn);
    cudaGetSymbolAddress((void**)&valh,  g_valh);
    cudaGetSymbolAddress((void**)&srch,  g_srch);
    cudaGetSymbolAddress((void**)&qh,    g_qh);
    cudaGetSymbolAddress((void**)&samph, g_samph);
    cudaGetSymbolAddress((void**)&xh,    g_xh);
    cudaGetSymbolAddress((void**)&hh,    g_hh);
    cudaGetSymbolAddress((void**)&wt,    g_wt);
    cudaGetSymbolAddress((void**)&boa,   g_boa);

    cudaFuncSetAttribute(gemm_f16<false, false>,
                         cudaFuncAttributeMaxDynamicSharedMemorySize, SMEM_BYTES);
    cudaFuncSetAttribute(gemm_f16<false, true>,
                         cudaFuncAttributeMaxDynamicSharedMemorySize, SMEM_BYTES);
    cudaFuncSetAttribute(gemm_f16<true, true>,
                         cudaFuncAttributeMaxDynamicSharedMemorySize, SMEM_BYTES);

    const int M = TOKENS;
    const int MB = (M + 127) / 128;
    dim3 thr(256);

    // all weight transposes + bias concat, one launch
    prep_weights<<<736, thr>>>(W_val, W_off, W_att, W_out, W1, W2, b_off, b_att, wt, boa);

    // srch = fp16(src); qh = fp16(src + pos)
    prep_h<<<(M * D_MODEL / 4 + 255) / 256, thr>>>(
        (const float4*)src, (const float4*)pos, (__half2*)srch, (__half2*)qh, M * D_MODEL / 4);

    // GEMMs (fp16 tensor cores, ldmatrix fragments, 2-stage BK=64)
    gemm_f16<false, true><<<dim3(4, MB), thr, SMEM_BYTES>>>(
        srch, wt + WT_VAL, b_val, valh, M, 256, 256);
    gemm_f16<false, false><<<dim3(6, MB), thr, SMEM_BYTES>>>(
        qh, wt + WT_OA, boa, oa, M, 384, 256);

    // sampler (softmax fused in-register)
    ms_sample_h<<<M / 2, thr>>>((const __half2*)valh, oa, ref, (__half2*)samph);

    gemm_f16<false, false><<<dim3(4, MB), thr, SMEM_BYTES>>>(
        samph, wt + WT_OUT, b_out, attno, M, 256, 256);

    add_layernorm<true><<<M, thr>>>(src, attno, ln1g, ln1b, x, xh);

    gemm_f16<true, true><<<dim3(16, MB), thr, SMEM_BYTES>>>(
        xh, wt + WT_W1, b1, hh, M, 1024, 256);
    gemm_f16<false, false><<<dim3(4, MB), thr, SMEM_BYTES>>>(
        hh, wt + WT_W2, b2, ffn, M, 256, 1024);

    add_layernorm<false><<<M, thr>>>(x, ffn, ln2g, ln2b, out, nullptr);
}

// round 16
// speedup vs baseline: 3.9407x; 1.1006x over previous
#include <cuda_runtime.h>
#include <cuda_fp16.h>
#include <cstdint>
#include <math.h>

// ---------------- static problem shape ----------------
#define BATCH     2
#define S_TOTAL   13294
#define TOKENS    (BATCH * S_TOTAL)     // 26588 = 4 * 6647
#define D_MODEL   256
#define D_FC      1024
#define N_HEADS   8
#define N_LEVELS  4
#define N_POINTS  4
#define D_HEAD    32

__device__ __constant__ int c_H[4]     = {100, 50, 25, 13};
__device__ __constant__ int c_W[4]     = {100, 50, 25, 13};
__device__ __constant__ int c_start[4] = {0, 10000, 12500, 13125};

// ---------------- scratch (no cudaMalloc allowed) ----------------
__device__ float  g_oa     [TOKENS * 384];       // fused [off(256) | attn_logits(128)]
__device__ float  g_attno  [TOKENS * D_MODEL];
__device__ float  g_x      [TOKENS * D_MODEL];
__device__ float  g_ffn    [TOKENS * D_MODEL];
__device__ __half g_valh   [TOKENS * D_MODEL];   // fp16 value projection
__device__ __half g_srch   [TOKENS * D_MODEL];   // fp16 src
__device__ __half g_qh     [TOKENS * D_MODEL];   // fp16 q = src+pos
__device__ __half g_samph  [TOKENS * D_MODEL];   // fp16 sampled
__device__ __half g_xh     [TOKENS * D_MODEL];   // fp16 LN1 out
__device__ __half g_hh     [TOKENS * D_FC];      // fp16 ffn hidden
__device__ __half g_wt     [753664];             // fp16 transposed weights [N][K]
__device__ float  g_boa    [384];                // concat bias off|attn

// offsets in g_wt (halves)
#define WT_VAL 0
#define WT_OA  65536          // 384 x 256
#define WT_OUT 163840         // 256 x 256
#define WT_W1  229376         // 1024 x 256
#define WT_W2  491520         // 256 x 1024

// ---------------- mma fp16 helper ----------------
__device__ __forceinline__ void mma_f16(float& d0, float& d1, float& d2, float& d3,
                                        uint32_t a0, uint32_t a1, uint32_t a2, uint32_t a3,
                                        uint32_t b0, uint32_t b1) {
    asm volatile(
        "mma.sync.aligned.m16n8k16.row.col.f32.f16.f16.f32 "
        "{%0,%1,%2,%3}, {%4,%5,%6,%7}, {%8,%9}, {%0,%1,%2,%3};\n"
        : "+f"(d0), "+f"(d1), "+f"(d2), "+f"(d3)
        : "r"(a0), "r"(a1), "r"(a2), "r"(a3), "r"(b0), "r"(b1));
}

// ---------------- ldmatrix helper ----------------
__device__ __forceinline__ void ldsm4(uint32_t& r0, uint32_t& r1, uint32_t& r2, uint32_t& r3,
                                      uint32_t addr) {
    asm volatile("ldmatrix.sync.aligned.m8n8.x4.shared.b16 {%0,%1,%2,%3}, [%4];\n"
                 : "=r"(r0), "=r"(r1), "=r"(r2), "=r"(r3) : "r"(addr));
}

// ---------------- cp.async helpers ----------------
__device__ __forceinline__ void cp16p(uint32_t smem_addr, const void* gmem, bool pred) {
    int sz = pred ? 16 : 0;
    asm volatile("cp.async.cg.shared.global [%0], [%1], 16, %2;\n"
                 :: "r"(smem_addr), "l"(gmem), "r"(sz));
}
__device__ __forceinline__ void cp16(uint32_t smem_addr, const void* gmem) {
    asm volatile("cp.async.cg.shared.global [%0], [%1], 16;\n"
                 :: "r"(smem_addr), "l"(gmem));
}

// ---------------- fused weight prep: 5 transposes + bias concat, one launch -------
__global__ void __launch_bounds__(256) prep_weights(
        const float* __restrict__ Wv, const float* __restrict__ Wo,
        const float* __restrict__ Wa, const float* __restrict__ Wu,
        const float* __restrict__ W1, const float* __restrict__ W2,
        const float* __restrict__ b_off, const float* __restrict__ b_att,
        __half* __restrict__ wt, float* __restrict__ boa) {
    const int tid = threadIdx.x;
    const int bx  = blockIdx.x;
    if (bx == 0) {
        boa[tid] = b_off[tid];
        if (tid < 128) boa[256 + tid] = b_att[tid];
    }

    const float* in; __half* out;
    int K, N, rowOff, base, tilesX;
    if      (bx < 64)  { in = Wv; out = wt + WT_VAL; K = 256;  N = 256;  rowOff = 0;   base = 0;   tilesX = 8;  }
    else if (bx < 128) { in = Wo; out = wt + WT_OA;  K = 256;  N = 256;  rowOff = 0;   base = 64;  tilesX = 8;  }
    else if (bx < 160) { in = Wa; out = wt + WT_OA;  K = 256;  N = 128;  rowOff = 256; base = 128; tilesX = 4;  }
    else if (bx < 224) { in = Wu; out = wt + WT_OUT; K = 256;  N = 256;  rowOff = 0;   base = 160; tilesX = 8;  }
    else if (bx < 480) { in = W1; out = wt + WT_W1;  K = 256;  N = 1024; rowOff = 0;   base = 224; tilesX = 32; }
    else               { in = W2; out = wt + WT_W2;  K = 1024; N = 256;  rowOff = 0;   base = 480; tilesX = 8;  }

    const int local = bx - base;
    const int n0 = (local % tilesX) * 32;
    const int k0 = (local / tilesX) * 32;

    __shared__ float t[32][33];
    const int tx = tid & 31, ty = tid >> 5;
    #pragma unroll
    for (int i = 0; i < 32; i += 8)
        t[ty + i][tx] = in[(size_t)(k0 + ty + i) * N + n0 + tx];
    __syncthreads();
    #pragma unroll
    for (int i = 0; i < 32; i += 8)
        out[(size_t)(rowOff + n0 + ty + i) * K + k0 + tx] = __float2half(t[tx][ty + i]);
}

// ---------------- fused: srch = fp16(src); qh = fp16(src + pos) ----------------
__global__ void prep_h(const float4* __restrict__ src, const float4* __restrict__ pos,
                       __half2* __restrict__ srch, __half2* __restrict__ qh, int n4) {
    int i = blockIdx.x * blockDim.x + threadIdx.x;
    if (i < n4) {
        float4 s = src[i], p = pos[i];
        srch[2 * i]     = __floats2half2_rn(s.x, s.y);
        srch[2 * i + 1] = __floats2half2_rn(s.z, s.w);
        qh[2 * i]       = __floats2half2_rn(s.x + p.x, s.y + p.y);
        qh[2 * i + 1]   = __floats2half2_rn(s.z + p.z, s.w + p.w);
    }
}

// ---------------- fp16 tensor-core GEMM, 2-stage cp.async, BK=64, ldmatrix --------
// BM=128, BN=64, BK=64, 256 threads (8 warps, 4x2), warp tile 32x32, m16n8k16.
// smem row pitch = 144B: conflict-free for cp.async stores and ldmatrix.
// __launch_bounds__(256, 4): target 4 CTAs/SM (occupancy probe).
#define AROW_B  144
#define A_STAGE (128 * AROW_B)            // 18432 B
#define B_STAGE (64 * AROW_B)             // 9216 B
#define STAGE_B (A_STAGE + B_STAGE)       // 27648 B
#define SMEM_BYTES (2 * STAGE_B)          // 55296 B

template<bool RELU, bool HALF_OUT>
__global__ void __launch_bounds__(256, 4) gemm_f16(
        const __half* __restrict__ A, const __half* __restrict__ Bt,
        const float* __restrict__ bias, void* __restrict__ Cv,
        int M, int N, int K) {
    extern __shared__ uint32_t smem[];
    const uint32_t sS = (uint32_t)__cvta_generic_to_shared(smem);

    const int tid  = threadIdx.x;
    const int lane = tid & 31;
    const int warp = tid >> 5;
    const int wm   = warp & 3;
    const int wn   = warp >> 2;
    const int row0 = blockIdx.y * 128;
    const int col0 = blockIdx.x * 64;

    const int ntiles = K >> 6;            // BK=64

    auto issue = [&](int kt, int st) {
        const int kg = kt << 6;
        const uint32_t aB = sS + st * STAGE_B;
        const uint32_t bB = aB + A_STAGE;
        #pragma unroll
        for (int i = 0; i < 4; i++) {
            int cid = tid + (i << 8);
            int m = cid >> 3;
            int c = cid & 7;
            int gr = row0 + m;
            bool ok = gr < M;
            const __half* g = A + (size_t)(ok ? gr : 0) * K + kg + c * 8;
            cp16p(aB + m * AROW_B + c * 16, g, ok);
        }
        #pragma unroll
        for (int i = 0; i < 2; i++) {
            int cid = tid + (i << 8);
            int n = cid >> 3;
            int c = cid & 7;
            const __half* g = Bt + (size_t)(col0 + n) * K + kg + c * 8;
            cp16(bB + n * AROW_B + c * 16, g);
        }
        asm volatile("cp.async.commit_group;\n");
    };

    float acc[2][4][4];
    #pragma unroll
    for (int t = 0; t < 2; t++)
        #pragma unroll
        for (int n = 0; n < 4; n++)
            #pragma unroll
            for (int j = 0; j < 4; j++) acc[t][n][j] = 0.f;

    issue(0, 0);

    const uint32_t aOff = (uint32_t)((wm * 32 + (lane & 15)) * AROW_B + (lane >> 4) * 16);
    const uint32_t bOff = (uint32_t)((wn * 32 + ((lane >> 4) & 1) * 8 + (lane & 7)) * AROW_B
                                     + ((lane >> 3) & 1) * 16);

    for (int kt = 0; kt < ntiles; kt++) {
        asm volatile("cp.async.wait_group 0;\n");
        __syncthreads();
        if (kt + 1 < ntiles) issue(kt + 1, (kt + 1) & 1);

        const int st = kt & 1;
        const uint32_t aBase = sS + st * STAGE_B + aOff;
        const uint32_t bBase = sS + st * STAGE_B + A_STAGE + bOff;

        #pragma unroll
        for (int ks = 0; ks < 4; ks++) {
            uint32_t af[2][4];
            #pragma unroll
            for (int t = 0; t < 2; t++)
                ldsm4(af[t][0], af[t][1], af[t][2], af[t][3],
                      aBase + t * (16 * AROW_B) + ks * 32);
            uint32_t bf[4][2];
            #pragma unroll
            for (int j = 0; j < 2; j++)
                ldsm4(bf[2 * j][0], bf[2 * j][1], bf[2 * j + 1][0], bf[2 * j + 1][1],
                      bBase + j * (16 * AROW_B) + ks * 32);
            #pragma unroll
            for (int t = 0; t < 2; t++)
                #pragma unroll
                for (int n = 0; n < 4; n++)
                    mma_f16(acc[t][n][0], acc[t][n][1], acc[t][n][2], acc[t][n][3],
                            af[t][0], af[t][1], af[t][2], af[t][3],
                            bf[n][0], bf[n][1]);
        }
    }

    // ---- epilogue ----
    const int q = lane & 3;
    const int r = lane >> 2;
    #pragma unroll
    for (int t = 0; t < 2; t++) {
        #pragma unroll
        for (int n = 0; n < 4; n++) {
            int gr = row0 + wm * 32 + t * 16 + r;
            int gc = col0 + wn * 32 + n * 8 + 2 * q;
            float b0 = bias[gc], b1 = bias[gc + 1];
            #pragma unroll
            for (int half_ = 0; half_ < 2; half_++) {
                int grr = gr + 8 * half_;
                if (grr >= M) continue;
                float v0 = acc[t][n][2 * half_]     + b0;
                float v1 = acc[t][n][2 * half_ + 1] + b1;
                if (RELU) { v0 = fmaxf(v0, 0.f); v1 = fmaxf(v1, 0.f); }
                if (HALF_OUT) {
                    __half2* C = (__half2*)Cv;
                    C[((size_t)grr * N + gc) >> 1] = __floats2half2_rn(v0, v1);
                } else {
                    float* C = (float*)Cv;
                    C[(size_t)grr * N + gc]     = v0;
                    C[(size_t)grr * N + gc + 1] = v1;
                }
            }
        }
    }
}

// ---------------- multi-scale deformable sampling, fused softmax -----------------
__global__ void ms_sample_h(const __half2* __restrict__ valh, const float* __restrict__ oa,
                            const float* __restrict__ ref, __half2* __restrict__ out) {
    const int warp = threadIdx.x >> 5;
    const int lane = threadIdx.x & 31;
    const int token = blockIdx.x * 2 + (warp >> 2);
    const int h  = ((warp & 3) << 1) + (lane >> 4);   // head 0..7
    const int cp = lane & 15;                         // channel pair 0..15
    const int b = token / S_TOTAL;

    const float* refp  = ref + (size_t)token * (N_LEVELS * 2);
    const float* offp  = oa  + (size_t)token * 384 + h * 32;
    const float* attnp = oa  + (size_t)token * 384 + 256 + h * 16;
    const __half2* vbase = valh + (size_t)b * S_TOTAL * 128 + h * 16 + cp;

    // ---- in-register softmax over the 16-lane group ----
    float logit = attnp[cp];
    float m_ = logit;
    #pragma unroll
    for (int o = 8; o > 0; o >>= 1) m_ = fmaxf(m_, __shfl_xor_sync(0xffffffffu, m_, o));
    float e = __expf(logit - m_);
    float ssum = e;
    #pragma unroll
    for (int o = 8; o > 0; o >>= 1) ssum += __shfl_xor_sync(0xffffffffu, ssum, o);
    const float aval = e / ssum;
    const int grp = lane & 16;

    float2 acc = make_float2(0.f, 0.f);
    #pragma unroll
    for (int l = 0; l < N_LEVELS; l++) {
        const int Hl = c_H[l], Wl = c_W[l];
        const float fH = (float)Hl, fW = (float)Wl;
        const float rx = refp[l * 2 + 0];
        const float ry = refp[l * 2 + 1];
        const __half2* vlev = vbase + (size_t)c_start[l] * 128;
        #pragma unroll
        for (int p = 0; p < N_POINTS; p++) {
            float ox = offp[l * 8 + p * 2 + 0];
            float oy = offp[l * 8 + p * 2 + 1];
            float px = (rx + ox / fW) * fW - 0.5f;
            float py = (ry + oy / fH) * fH - 0.5f;
            float x0 = floorf(px), y0 = floorf(py);
            float wx = px - x0, wy = py - y0;
            int x0i = (int)x0, y0i = (int)y0;
            float a = __shfl_sync(0xffffffffu, aval, grp | (l * 4 + p));

            float2 s = make_float2(0.f, 0.f);
            {
                if (x0i >= 0 && x0i < Wl && y0i >= 0 && y0i < Hl) {
                    float w = (1.f - wx) * (1.f - wy);
                    float2 v = __half22float2(vlev[(size_t)(y0i * Wl + x0i) * 128]);
                    s.x += w * v.x; s.y += w * v.y;
                }
            }
            {
                int xi = x0i + 1;
                if (xi >= 0 && xi < Wl && y0i >= 0 && y0i < Hl) {
                    float w = wx * (1.f - wy);
                    float2 v = __half22float2(vlev[(size_t)(y0i * Wl + xi) * 128]);
                    s.x += w * v.x; s.y += w * v.y;
                }
            }
            {
                int yi = y0i + 1;
                if (x0i >= 0 && x0i < Wl && yi >= 0 && yi < Hl) {
                    float w = (1.f - wx) * wy;
                    float2 v = __half22float2(vlev[(size_t)(yi * Wl + x0i) * 128]);
                    s.x += w * v.x; s.y += w * v.y;
                }
            }
            {
                int xi = x0i + 1, yi = y0i + 1;
                if (xi >= 0 && xi < Wl && yi >= 0 && yi < Hl) {
                    float w = wx * wy;
                    float2 v = __half22float2(vlev[(size_t)(yi * Wl + xi) * 128]);
                    s.x += w * v.x; s.y += w * v.y;
                }
            }
            acc.x += a * s.x;
            acc.y += a * s.y;
        }
    }
    out[(size_t)token * 128 + h * 16 + cp] = __floats2half2_rn(acc.x, acc.y);
}

// ---------------- residual add + LayerNorm, float4 lanes, 4 tokens/block ----------
// 64 threads per token (one float4 each); TOKENS % 4 == 0.
template<bool HALF_AUX>
__global__ void __launch_bounds__(256) add_layernorm4(
        const float4* __restrict__ a, const float4* __restrict__ b,
        const float4* __restrict__ gamma, const float4* __restrict__ beta,
        float4* __restrict__ out, __half2* __restrict__ outh) {
    __shared__ float red1[4][2];
    __shared__ float red2[4][2];
    const int grp = threadIdx.x >> 6;          // token group 0..3
    const int t64 = threadIdx.x & 63;          // 0..63
    const int w   = t64 >> 5;                  // warp-within-group
    const int token = blockIdx.x * 4 + grp;

    float4 av = a[(size_t)token * 64 + t64];
    float4 bv = b[(size_t)token * 64 + t64];
    float4 v = make_float4(av.x + bv.x, av.y + bv.y, av.z + bv.z, av.w + bv.w);

    float s = v.x + v.y + v.z + v.w;
    #pragma unroll
    for (int o = 16; o > 0; o >>= 1) s += __shfl_xor_sync(0xffffffffu, s, o);
    if ((t64 & 31) == 0) red1[grp][w] = s;
    __syncthreads();
    float mu = (red1[grp][0] + red1[grp][1]) * (1.f / D_MODEL);

    float4 d = make_float4(v.x - mu, v.y - mu, v.z - mu, v.w - mu);
    float ss = d.x * d.x + d.y * d.y + d.z * d.z + d.w * d.w;
    #pragma unroll
    for (int o = 16; o > 0; o >>= 1) ss += __shfl_xor_sync(0xffffffffu, ss, o);
    if ((t64 & 31) == 0) red2[grp][w] = ss;
    __syncthreads();
    float var = (red2[grp][0] + red2[grp][1]) * (1.f / D_MODEL);
    float inv = rsqrtf(var + 1e-5f);

    float4 g = gamma[t64], be = beta[t64];
    float4 o4 = make_float4(d.x * inv * g.x + be.x, d.y * inv * g.y + be.y,
                            d.z * inv * g.z + be.z, d.w * inv * g.w + be.w);
    out[(size_t)token * 64 + t64] = o4;
    if (HALF_AUX) {
        outh[(size_t)token * 128 + t64 * 2]     = __floats2half2_rn(o4.x, o4.y);
        outh[(size_t)token * 128 + t64 * 2 + 1] = __floats2half2_rn(o4.z, o4.w);
    }
}

// ---------------- launch ----------------
extern "C" void kernel_launch(void* const* d_in, const int* in_sizes, int n_in,
                              void* d_out, int out_size) {
    const float* src   = (const float*)d_in[0];
    const float* pos   = (const float*)d_in[1];
    const float* ref   = (const float*)d_in[2];
    const float* W_off = (const float*)d_in[5];
    const float* b_off = (const float*)d_in[6];
    const float* W_att = (const float*)d_in[7];
    const float* b_att = (const float*)d_in[8];
    const float* W_val = (const float*)d_in[9];
    const float* b_val = (const float*)d_in[10];
    const float* W_out = (const float*)d_in[11];
    const float* b_out = (const float*)d_in[12];
    const float* ln1g  = (const float*)d_in[13];
    const float* ln1b  = (const float*)d_in[14];
    const float* W1    = (const float*)d_in[15];
    const float* b1    = (const float*)d_in[16];
    const float* W2    = (const float*)d_in[17];
    const float* b2    = (const float*)d_in[18];
    const float* ln2g  = (const float*)d_in[19];
    const float* ln2b  = (const float*)d_in[20];
    float* out = (float*)d_out;

    float  *oa, *attno, *x, *ffn, *boa;
    __half *valh, *srch, *qh, *samph, *xh, *hh, *wt;
    cudaGetSymbolAddress((void**)&oa,    g_oa);
    cudaGetSymbolAddress((void**)&attno, g_attno);
    cudaGetSymbolAddress((void**)&x,     g_x);
    cudaGetSymbolAddress((void**)&ffn,   g_ffn);
    cudaGetSymbolAddress((void**)&valh,  g_valh);
    cudaGetSymbolAddress((void**)&srch,  g_srch);
    cudaGetSymbolAddress((void**)&qh,    g_qh);
    cudaGetSymbolAddress((void**)&samph, g_samph);
    cudaGetSymbolAddress((void**)&xh,    g_xh);
    cudaGetSymbolAddress((void**)&hh,    g_hh);
    cudaGetSymbolAddress((void**)&wt,    g_wt);
    cudaGetSymbolAddress((void**)&boa,   g_boa);

    cudaFuncSetAttribute(gemm_f16<false, false>,
                         cudaFuncAttributeMaxDynamicSharedMemorySize, SMEM_BYTES);
    cudaFuncSetAttribute(gemm_f16<false, true>,
                         cudaFuncAttributeMaxDynamicSharedMemorySize, SMEM_BYTES);
    cudaFuncSetAttribute(gemm_f16<true, true>,
                         cudaFuncAttributeMaxDynamicSharedMemorySize, SMEM_BYTES);

    const int M = TOKENS;
    const int MB = (M + 127) / 128;
    dim3 thr(256);

    // all weight transposes + bias concat, one launch
    prep_weights<<<736, thr>>>(W_val, W_off, W_att, W_out, W1, W2, b_off, b_att, wt, boa);

    // srch = fp16(src); qh = fp16(src + pos)
    prep_h<<<(M * D_MODEL / 4 + 255) / 256, thr>>>(
        (const float4*)src, (const float4*)pos, (__half2*)srch, (__half2*)qh, M * D_MODEL / 4);

    // GEMMs (fp16 tensor cores, ldmatrix fragments, 2-stage BK=64, 4 CTA/SM)
    gemm_f16<false, true><<<dim3(4, MB), thr, SMEM_BYTES>>>(
        srch, wt + WT_VAL, b_val, valh, M, 256, 256);
    gemm_f16<false, false><<<dim3(6, MB), thr, SMEM_BYTES>>>(
        qh, wt + WT_OA, boa, oa, M, 384, 256);

    // sampler (softmax fused in-register)
    ms_sample_h<<<M / 2, thr>>>((const __half2*)valh, oa, ref, (__half2*)samph);

    gemm_f16<false, false><<<dim3(4, MB), thr, SMEM_BYTES>>>(
        samph, wt + WT_OUT, b_out, attno, M, 256, 256);

    add_layernorm4<true><<<M / 4, thr>>>(
        (const float4*)src, (const float4*)attno, (const float4*)ln1g, (const float4*)ln1b,
        (float4*)x, (__half2*)xh);

    gemm_f16<true, true><<<dim3(16, MB), thr, SMEM_BYTES>>>(
        xh, wt + WT_W1, b1, hh, M, 1024, 256);
    gemm_f16<false, false><<<dim3(4, MB), thr, SMEM_BYTES>>>(
        hh, wt + WT_W2, b2, ffn, M, 256, 1024);

    add_layernorm4<false><<<M / 4, thr>>>(
        (const float4*)x, (const float4*)ffn, (const float4*)ln2g, (const float4*)ln2b,
        (float4*)out, nullptr);
}